// round 7
// baseline (speedup 1.0000x reference)
#include <cuda_runtime.h>
#include <cuda_bf16.h>
#include <cstdint>
#include <math.h>

#define SEQL   2048
#define BSZ    2
#define ROWS   (BSZ*SEQL)          // 4096
#define DIMX   2048
#define QLORA  1536
#define KVLORA 512
#define NHEADS 16
#define QKHD   192
#define NOPE_D 128
#define ROPE_D 64
#define VHD    128

// ---------------- scratch (static device globals; no allocation) ----------------
__device__ float g_qa [ROWS*QLORA];
__device__ float g_qb [ROWS*(NHEADS*QKHD)];
__device__ float g_kva[ROWS*(KVLORA+ROPE_D)];
__device__ float g_kvb[ROWS*(NHEADS*(NOPE_D+VHD))];

__device__ __nv_bfloat16 g_xh  [ROWS*DIMX],   g_xl  [ROWS*DIMX];
__device__ __nv_bfloat16 g_qah [ROWS*QLORA],  g_qal [ROWS*QLORA];
__device__ __nv_bfloat16 g_kvch[ROWS*KVLORA], g_kvcl[ROWS*KVLORA];
__device__ __nv_bfloat16 g_atth[ROWS*2048],   g_attl[ROWS*2048];
__device__ __nv_bfloat16 g_wqah[QLORA*DIMX],  g_wqal[QLORA*DIMX];
__device__ __nv_bfloat16 g_wqbh[3072*QLORA],  g_wqbl[3072*QLORA];
__device__ __nv_bfloat16 g_wkvah[576*DIMX],   g_wkval[576*DIMX];
__device__ __nv_bfloat16 g_wkvbh[4096*KVLORA],g_wkvbl[4096*KVLORA];
__device__ __nv_bfloat16 g_woh [DIMX*2048],   g_wol [DIMX*2048];
// head-major bf16 K-full (192, rope folded) and V planes for flash
__device__ __nv_bfloat16 g_kfh[ROWS*NHEADS*QKHD], g_kfl[ROWS*NHEADS*QKHD];
__device__ __nv_bfloat16 g_vfh[ROWS*NHEADS*VHD],  g_vfl[ROWS*NHEADS*VHD];

__device__ __forceinline__ uint32_t smem_to_u32(const void* p) {
    uint32_t a;
    asm("{ .reg .u64 t; cvta.to.shared.u64 t, %1; cvt.u32.u64 %0, t; }" : "=r"(a) : "l"(p));
    return a;
}
#define SWZ(x) ((x) ^ (((x) >> 3) & 0x70))

__device__ __forceinline__ void ldmatrix_x4(uint32_t* r, uint32_t addr) {
    asm volatile("ldmatrix.sync.aligned.m8n8.x4.shared.b16 {%0,%1,%2,%3}, [%4];"
        : "=r"(r[0]), "=r"(r[1]), "=r"(r[2]), "=r"(r[3]) : "r"(addr));
}
__device__ __forceinline__ void ldmatrix_x4_trans(uint32_t* r, uint32_t addr) {
    asm volatile("ldmatrix.sync.aligned.m8n8.x4.trans.shared.b16 {%0,%1,%2,%3}, [%4];"
        : "=r"(r[0]), "=r"(r[1]), "=r"(r[2]), "=r"(r[3]) : "r"(addr));
}
__device__ __forceinline__ void mma_bf16(float* c, const uint32_t* a, uint32_t b0, uint32_t b1) {
    asm volatile(
        "mma.sync.aligned.m16n8k16.row.col.f32.bf16.bf16.f32 "
        "{%0,%1,%2,%3}, {%4,%5,%6,%7}, {%8,%9}, {%0,%1,%2,%3};"
        : "+f"(c[0]), "+f"(c[1]), "+f"(c[2]), "+f"(c[3])
        : "r"(a[0]), "r"(a[1]), "r"(a[2]), "r"(a[3]), "r"(b0), "r"(b1));
}
__device__ __forceinline__ uint32_t pack_bf16x2(float lo, float hi) {
    __nv_bfloat162 h = __floats2bfloat162_rn(lo, hi);
    return *reinterpret_cast<uint32_t*>(&h);
}
__device__ __forceinline__ void cp_async16(uint32_t dst, const void* src) {
    asm volatile("cp.async.cg.shared.global [%0], [%1], 16;" :: "r"(dst), "l"(src));
}
#define CP_COMMIT() asm volatile("cp.async.commit_group;" ::: "memory")
#define CP_WAIT1()  asm volatile("cp.async.wait_group 1;" ::: "memory")
#define CP_WAIT0()  asm volatile("cp.async.wait_group 0;" ::: "memory")

// ---------------- fp32 -> bf16 hi/lo planar converter ----------------
__global__ __launch_bounds__(256)
void cvt_hilo(const float* __restrict__ s, __nv_bfloat16* __restrict__ hi,
              __nv_bfloat16* __restrict__ lo, int n)
{
    int i = (blockIdx.x * 256 + threadIdx.x) * 4;
    if (i >= n) return;
    float4 v = *reinterpret_cast<const float4*>(s + i);
    __nv_bfloat162 h01 = __floats2bfloat162_rn(v.x, v.y);
    __nv_bfloat162 h23 = __floats2bfloat162_rn(v.z, v.w);
    __nv_bfloat162 l01 = __floats2bfloat162_rn(v.x - __bfloat162float(h01.x),
                                               v.y - __bfloat162float(h01.y));
    __nv_bfloat162 l23 = __floats2bfloat162_rn(v.z - __bfloat162float(h23.x),
                                               v.w - __bfloat162float(h23.y));
    *reinterpret_cast<uint2*>(hi + i) =
        make_uint2(*reinterpret_cast<uint32_t*>(&h01), *reinterpret_cast<uint32_t*>(&h23));
    *reinterpret_cast<uint2*>(lo + i) =
        make_uint2(*reinterpret_cast<uint32_t*>(&l01), *reinterpret_cast<uint32_t*>(&l23));
}

// ---------------- build head-major K-full / V bf16 hi/lo for flash ----------------
__global__ __launch_bounds__(256)
void cvt_kv(const float* __restrict__ kvb, const float* __restrict__ kva,
            __nv_bfloat16* __restrict__ kfh, __nv_bfloat16* __restrict__ kfl,
            __nv_bfloat16* __restrict__ vfh, __nv_bfloat16* __restrict__ vfl)
{
    int row = blockIdx.x;               // 0..4095
    // chunks of 4 floats: 0..511 K-nope, 512..767 K-rope, 768..1279 V
    for (int c = threadIdx.x; c < 1280; c += 256) {
        float4 v;
        __nv_bfloat16 *dh, *dl;
        if (c < 512) {
            int h = c >> 5, d = (c & 31) * 4;
            v = *reinterpret_cast<const float4*>(kvb + (size_t)row*4096 + h*256 + d);
            dh = kfh + ((size_t)row*NHEADS + h)*QKHD + d;
            dl = kfl + ((size_t)row*NHEADS + h)*QKHD + d;
        } else if (c < 768) {
            int cc = c - 512;
            int h = cc >> 4, d2 = (cc & 15) * 4;
            v = *reinterpret_cast<const float4*>(kva + (size_t)row*576 + 512 + d2);
            dh = kfh + ((size_t)row*NHEADS + h)*QKHD + 128 + d2;
            dl = kfl + ((size_t)row*NHEADS + h)*QKHD + 128 + d2;
        } else {
            int cc = c - 768;
            int h = cc >> 5, d = (cc & 31) * 4;
            v = *reinterpret_cast<const float4*>(kvb + (size_t)row*4096 + h*256 + 128 + d);
            dh = vfh + ((size_t)row*NHEADS + h)*VHD + d;
            dl = vfl + ((size_t)row*NHEADS + h)*VHD + d;
        }
        __nv_bfloat162 h01 = __floats2bfloat162_rn(v.x, v.y);
        __nv_bfloat162 h23 = __floats2bfloat162_rn(v.z, v.w);
        __nv_bfloat162 l01 = __floats2bfloat162_rn(v.x - __bfloat162float(h01.x),
                                                   v.y - __bfloat162float(h01.y));
        __nv_bfloat162 l23 = __floats2bfloat162_rn(v.z - __bfloat162float(h23.x),
                                                   v.w - __bfloat162float(h23.y));
        *reinterpret_cast<uint2*>(dh) =
            make_uint2(*reinterpret_cast<uint32_t*>(&h01), *reinterpret_cast<uint32_t*>(&h23));
        *reinterpret_cast<uint2*>(dl) =
            make_uint2(*reinterpret_cast<uint32_t*>(&l01), *reinterpret_cast<uint32_t*>(&l23));
    }
}

// ============ cp.async 2-stage split-bf16 HMMA GEMM, CTA 128x256, warp 64x64 ============
#define GB_STAGE 98304
#define GB_SMEM  (2*GB_STAGE + 128)

__global__ __launch_bounds__(256, 1)
void gemm_bf(const __nv_bfloat16* __restrict__ Ah, const __nv_bfloat16* __restrict__ Al, int lda,
             const __nv_bfloat16* __restrict__ Bh, const __nv_bfloat16* __restrict__ Bl, int ldw,
             const float* __restrict__ bias,
             float* __restrict__ C, int ldc,
             int Nn, int K)
{
    extern __shared__ char smraw[];
    uint32_t sb0 = smem_to_u32(smraw);
    uint32_t sb = (sb0 + 127u) & ~127u;

    const int tid  = threadIdx.x;
    const int lane = tid & 31;
    const int wid  = tid >> 5;
    const int bm = blockIdx.y * 128;
    const int bn = blockIdx.x * 256;
    const int wm = (wid & 1) * 64;
    const int wn = (wid >> 1) * 64;
    const int nk = K >> 6;

    float acc[4][8][4];
#pragma unroll
    for (int mt = 0; mt < 4; mt++)
#pragma unroll
        for (int nt = 0; nt < 8; nt++)
#pragma unroll
            for (int q = 0; q < 4; q++) acc[mt][nt][q] = 0.f;

#define GB_ISSUE(kt_) do {                                                      \
        const uint32_t stb = sb + (uint32_t)((kt_) & 1) * GB_STAGE;             \
        const int k0_ = (kt_) << 6;                                             \
        _Pragma("unroll")                                                       \
        for (int i = 0; i < 4; i++) {                                           \
            const int idx = (i << 8) + tid;                                     \
            const int r = idx >> 3;                                             \
            const int c = idx & 7;                                              \
            uint32_t off = SWZ((uint32_t)(r*128 + c*16));                       \
            cp_async16(stb + off,          Ah + (size_t)(bm + r)*lda + k0_ + c*8); \
            cp_async16(stb + 16384u + off, Al + (size_t)(bm + r)*lda + k0_ + c*8); \
        }                                                                       \
        _Pragma("unroll")                                                       \
        for (int i = 0; i < 8; i++) {                                           \
            const int idx = (i << 8) + tid;                                     \
            const int r = idx >> 3;                                             \
            const int c = idx & 7;                                              \
            int rr = bn + r; if (rr >= Nn) rr = Nn - 1;                         \
            uint32_t off = SWZ((uint32_t)(r*128 + c*16));                       \
            cp_async16(stb + 32768u + off, Bh + (size_t)rr*ldw + k0_ + c*8);    \
            cp_async16(stb + 65536u + off, Bl + (size_t)rr*ldw + k0_ + c*8);    \
        }                                                                       \
    } while (0)

    GB_ISSUE(0); CP_COMMIT();

    for (int kt = 0; kt < nk; kt++) {
        if (kt + 1 < nk) { GB_ISSUE(kt + 1); }
        CP_COMMIT();
        CP_WAIT1();
        __syncthreads();

        const uint32_t baseA = sb + (uint32_t)(kt & 1) * GB_STAGE;
        const uint32_t baseB = baseA + 32768u;
#pragma unroll
        for (int k16 = 0; k16 < 4; k16++) {
            uint32_t ah[4][4], al[4][4];
#pragma unroll
            for (int mt = 0; mt < 4; mt++) {
                uint32_t row = wm + mt*16 + (lane & 15);
                uint32_t off = SWZ(row*128u + (uint32_t)(k16*32) + ((lane >> 4) << 4));
                ldmatrix_x4(ah[mt], baseA + off);
                ldmatrix_x4(al[mt], baseA + 16384u + off);
            }
#pragma unroll
            for (int g = 0; g < 4; g++) {
                uint32_t bh[4], bl[4];
                uint32_t nrow = wn + g*16 + ((lane >> 4) << 3) + (lane & 7);
                uint32_t off = SWZ(nrow*128u + (uint32_t)(k16*32) + (((lane >> 3) & 1) << 4));
                ldmatrix_x4(bh, baseB + off);
                ldmatrix_x4(bl, baseB + 32768u + off);
#pragma unroll
                for (int mt = 0; mt < 4; mt++) {
                    float* a0 = acc[mt][2*g];
                    float* a1 = acc[mt][2*g+1];
                    mma_bf16(a0, ah[mt], bh[0], bh[1]);
                    mma_bf16(a0, ah[mt], bl[0], bl[1]);
                    mma_bf16(a0, al[mt], bh[0], bh[1]);
                    mma_bf16(a1, ah[mt], bh[2], bh[3]);
                    mma_bf16(a1, ah[mt], bl[2], bl[3]);
                    mma_bf16(a1, al[mt], bh[2], bh[3]);
                }
            }
        }
        __syncthreads();
    }

    // ---- epilogue ----
#pragma unroll
    for (int nt = 0; nt < 8; nt++) {
        int col = bn + wn + nt*8 + (lane & 3)*2;
        if (col >= Nn) continue;
        float bx = bias[col], by = bias[col+1];
#pragma unroll
        for (int mt = 0; mt < 4; mt++) {
            int row = bm + wm + mt*16 + (lane >> 2);
            *reinterpret_cast<float2*>(C + (size_t)row*ldc + col) =
                make_float2(acc[mt][nt][0] + bx, acc[mt][nt][1] + by);
            *reinterpret_cast<float2*>(C + (size_t)(row+8)*ldc + col) =
                make_float2(acc[mt][nt][2] + bx, acc[mt][nt][3] + by);
        }
    }
#undef GB_ISSUE
}

// ---------------- RMSNorm -> bf16 hi/lo planar ----------------
__global__ __launch_bounds__(256)
void rmsnorm_hilo(const float* __restrict__ src,
                  __nv_bfloat16* __restrict__ hi, __nv_bfloat16* __restrict__ lo,
                  const float* __restrict__ w, int width, int sstride, int dstride)
{
    int row = blockIdx.x;
    const float* s = src + (size_t)row * sstride;

    float ss = 0.f;
    for (int c = threadIdx.x; c < width; c += blockDim.x) { float v = s[c]; ss += v*v; }

    __shared__ float red[8];
#pragma unroll
    for (int off = 16; off; off >>= 1) ss += __shfl_xor_sync(0xffffffffu, ss, off);
    int warp = threadIdx.x >> 5;
    if ((threadIdx.x & 31) == 0) red[warp] = ss;
    __syncthreads();
    if (warp == 0) {
        float v = (threadIdx.x < 8) ? red[threadIdx.x] : 0.f;
#pragma unroll
        for (int off = 4; off; off >>= 1) v += __shfl_xor_sync(0xffffffffu, v, off);
        if (threadIdx.x == 0) red[0] = v;
    }
    __syncthreads();
    float scale = rsqrtf(red[0] / (float)width + 1e-6f);
    __nv_bfloat16* dh = hi + (size_t)row * dstride;
    __nv_bfloat16* dl = lo + (size_t)row * dstride;
    for (int c = threadIdx.x; c < width; c += blockDim.x) {
        float v = s[c] * scale * w[c];
        __nv_bfloat16 hv = __float2bfloat16_rn(v);
        dh[c] = hv;
        dl[c] = __float2bfloat16_rn(v - __bfloat162float(hv));
    }
}

// ---------------- RoPE ----------------
__global__ __launch_bounds__(256)
void rope_kernel(float* __restrict__ qb, float* __restrict__ kva)
{
    int row = blockIdx.x;
    int s = row & (SEQL - 1);
    for (int p = threadIdx.x; p < 544; p += blockDim.x) {
        int d = p & 31;
        float ang = (float)s * powf(10000.f, -(float)d * (1.f/32.f));
        float sn, c;
        sincosf(ang, &sn, &c);
        float* base;
        if (p < 512) {
            int hh = p >> 5;
            base = qb + (size_t)row*(NHEADS*QKHD) + hh*QKHD + NOPE_D;
        } else {
            base = kva + (size_t)row*(KVLORA+ROPE_D) + KVLORA;
        }
        float x1 = base[d], x2 = base[d+32];
        base[d]    = x1*c - x2*sn;
        base[d+32] = x2*c + x1*sn;
    }
}

// ============ Flash attention via mma.sync (split-bf16), cp.async K/V ============
#define FL_QH 0
#define FL_QL 49152
#define FL_KH 98304
#define FL_KL 122880
#define FL_VH 147456
#define FL_VL 163840
#define FL_SMEM 180224

__global__ __launch_bounds__(256, 1)
void flash_mma(const float* __restrict__ qb,
               const __nv_bfloat16* __restrict__ kfh, const __nv_bfloat16* __restrict__ kfl,
               const __nv_bfloat16* __restrict__ vfh, const __nv_bfloat16* __restrict__ vfl,
               __nv_bfloat16* __restrict__ atth,
               __nv_bfloat16* __restrict__ attl)
{
    extern __shared__ char smraw[];
    uint32_t sb0 = smem_to_u32(smraw);
    uint32_t sb = (sb0 + 127u) & ~127u;
    char* smp = smraw + (sb - sb0);

    const int qt = blockIdx.x;
    const int h  = blockIdx.y;
    const int b  = blockIdx.z;
    const int s0 = qt * 128;
    const int bb = b * SEQL;
    const int tid  = threadIdx.x;
    const int lane = tid & 31;
    const int wid  = tid >> 5;
    const int wrow = wid * 16;
    const float scale = 0.07216878364870323f;

    // ---- load Q (128 x 192), prescaled, hi/lo (once per block) ----
#pragma unroll
    for (int i = 0; i < 24; i++) {
        int idx = tid + i*256;
        int row = idx / 48;
        int d = (idx - row*48) * 4;
        float4 v = *reinterpret_cast<const float4*>(
            qb + (size_t)(bb + s0 + row)*3072 + h*192 + d);
        v.x *= scale; v.y *= scale; v.z *= scale; v.w *= scale;
        int ch = d >> 6, dc = d & 63;
        uint32_t off = SWZ((uint32_t)(row*128 + dc*2));
        __nv_bfloat162 h01 = __floats2bfloat162_rn(v.x, v.y);
        __nv_bfloat162 h23 = __floats2bfloat162_rn(v.z, v.w);
        __nv_bfloat162 l01 = __floats2bfloat162_rn(v.x - __bfloat162float(h01.x),
                                                   v.y - __bfloat162float(h01.y));
        __nv_bfloat162 l23 = __floats2bfloat162_rn(v.z - __bfloat162float(h23.x),
                                                   v.w - __bfloat162float(h23.y));
        *reinterpret_cast<uint2*>(smp + FL_QH + ch*16384 + off) =
            make_uint2(*reinterpret_cast<uint32_t*>(&h01), *reinterpret_cast<uint32_t*>(&h23));
        *reinterpret_cast<uint2*>(smp + FL_QL + ch*16384 + off) =
            make_uint2(*reinterpret_cast<uint32_t*>(&l01), *reinterpret_cast<uint32_t*>(&l23));
    }

    float oc[16][4];
#pragma unroll
    for (int nt = 0; nt < 16; nt++)
#pragma unroll
        for (int q = 0; q < 4; q++) oc[nt][q] = 0.f;
    float m0 = -1e30f, m1 = -1e30f, l0 = 0.f, l1 = 0.f;

    const int rg0 = s0 + wrow + (lane >> 2);
    const int rg1 = rg0 + 8;
    const int nkt = 2*qt + 2;

    for (int kt = 0; kt < nkt; kt++) {
        if (kt > 0) __syncthreads();     // all warps done with previous K/V smem
        const int ks0 = kt * 64;

        // ---- K tiles: 2 planes x 64 rows x 24 16B-chunks = 3072 chunks ----
#pragma unroll
        for (int i = 0; i < 12; i++) {
            int idx = tid + i*256;
            int plane = idx >> 11;       // 0:hi (idx<2048)? No: 3072 chunks -> see below
            // use explicit split: first 1536 = hi, next 1536 = lo
            int cidx = idx;
            const __nv_bfloat16* src;
            uint32_t base;
            if (cidx < 1536) { src = kfh; base = (uint32_t)FL_KH; }
            else             { src = kfl; base = (uint32_t)FL_KL; cidx -= 1536; }
            int row = cidx / 24;
            int c = cidx - row*24;
            int ch = c >> 3;
            int dc8 = (c & 7) * 8;
            uint32_t dst = sb + base + ch*8192u + SWZ((uint32_t)(row*128 + dc8*2));
            cp_async16(dst, src + ((size_t)(bb + ks0 + row)*NHEADS + h)*QKHD + ch*64 + dc8);
            (void)plane;
        }
        // ---- V tiles: 2 planes x 64 rows x 16 chunks = 2048 chunks ----
#pragma unroll
        for (int i = 0; i < 8; i++) {
            int idx = tid + i*256;
            int cidx = idx;
            const __nv_bfloat16* src;
            uint32_t base;
            if (cidx < 1024) { src = vfh; base = (uint32_t)FL_VH; }
            else             { src = vfl; base = (uint32_t)FL_VL; cidx -= 1024; }
            int row = cidx >> 4;
            int c = cidx & 15;
            int ch = c >> 3;
            int dc8 = (c & 7) * 8;
            uint32_t dst = sb + base + ch*8192u + SWZ((uint32_t)(row*128 + dc8*2));
            cp_async16(dst, src + ((size_t)(bb + ks0 + row)*NHEADS + h)*VHD + ch*64 + dc8);
        }
        CP_COMMIT();
        CP_WAIT0();
        __syncthreads();

        if (ks0 > s0 + wrow + 15) continue;

        float sc[8][4];
#pragma unroll
        for (int nt = 0; nt < 8; nt++)
#pragma unroll
            for (int q = 0; q < 4; q++) sc[nt][q] = 0.f;

#pragma unroll
        for (int ks = 0; ks < 12; ks++) {
            int ch = ks >> 2;
            uint32_t kb = (uint32_t)((ks & 3) * 32);
            uint32_t ah[4], al[4];
            {
                uint32_t row = wrow + (lane & 15);
                uint32_t off = SWZ(row*128u + kb + ((lane >> 4) << 4));
                ldmatrix_x4(ah, sb + FL_QH + ch*16384 + off);
                ldmatrix_x4(al, sb + FL_QL + ch*16384 + off);
            }
            uint32_t bh[16], bl[16];
#pragma unroll
            for (int ng = 0; ng < 4; ng++) {
                uint32_t nrow = ng*16 + ((lane >> 4) << 3) + (lane & 7);
                uint32_t off = SWZ(nrow*128u + kb + (((lane >> 3) & 1) << 4));
                ldmatrix_x4(&bh[ng*4], sb + FL_KH + ch*8192 + off);
                ldmatrix_x4(&bl[ng*4], sb + FL_KL + ch*8192 + off);
            }
#pragma unroll
            for (int nt = 0; nt < 8; nt++) {
                mma_bf16(sc[nt], ah, bh[nt*2], bh[nt*2+1]);
                mma_bf16(sc[nt], ah, bl[nt*2], bl[nt*2+1]);
                mma_bf16(sc[nt], al, bh[nt*2], bh[nt*2+1]);
            }
        }

        if (ks0 + 63 > s0 + wrow) {
#pragma unroll
            for (int nt = 0; nt < 8; nt++) {
                int colg = ks0 + nt*8 + (lane & 3)*2;
                if (colg     > rg0) sc[nt][0] = -1e30f;
                if (colg + 1 > rg0) sc[nt][1] = -1e30f;
                if (colg     > rg1) sc[nt][2] = -1e30f;
                if (colg + 1 > rg1) sc[nt][3] = -1e30f;
            }
        }

        float mx0 = -1e30f, mx1 = -1e30f;
#pragma unroll
        for (int nt = 0; nt < 8; nt++) {
            mx0 = fmaxf(mx0, fmaxf(sc[nt][0], sc[nt][1]));
            mx1 = fmaxf(mx1, fmaxf(sc[nt][2], sc[nt][3]));
        }
        mx0 = fmaxf(mx0, __shfl_xor_sync(0xffffffffu, mx0, 1));
        mx0 = fmaxf(mx0, __shfl_xor_sync(0xffffffffu, mx0, 2));
        mx1 = fmaxf(mx1, __shfl_xor_sync(0xffffffffu, mx1, 1));
        mx1 = fmaxf(mx1, __shfl_xor_sync(0xffffffffu, mx1, 2));
        float mn0 = fmaxf(m0, mx0), mn1 = fmaxf(m1, mx1);
        float a0 = __expf(m0 - mn0), a1 = __expf(m1 - mn1);
        m0 = mn0; m1 = mn1;
        float rs0 = 0.f, rs1 = 0.f;
#pragma unroll
        for (int nt = 0; nt < 8; nt++) {
            sc[nt][0] = __expf(sc[nt][0] - mn0); rs0 += sc[nt][0];
            sc[nt][1] = __expf(sc[nt][1] - mn0); rs0 += sc[nt][1];
            sc[nt][2] = __expf(sc[nt][2] - mn1); rs1 += sc[nt][2];
            sc[nt][3] = __expf(sc[nt][3] - mn1); rs1 += sc[nt][3];
        }
        rs0 += __shfl_xor_sync(0xffffffffu, rs0, 1);
        rs0 += __shfl_xor_sync(0xffffffffu, rs0, 2);
        rs1 += __shfl_xor_sync(0xffffffffu, rs1, 1);
        rs1 += __shfl_xor_sync(0xffffffffu, rs1, 2);
        l0 = l0*a0 + rs0;
        l1 = l1*a1 + rs1;
#pragma unroll
        for (int nt = 0; nt < 16; nt++) {
            oc[nt][0] *= a0; oc[nt][1] *= a0;
            oc[nt][2] *= a1; oc[nt][3] *= a1;
        }

#pragma unroll
        for (int kp = 0; kp < 4; kp++) {
            uint32_t ph[4], pl[4];
            {
                float p0 = sc[2*kp][0],  p1 = sc[2*kp][1];
                float p2 = sc[2*kp][2],  p3 = sc[2*kp][3];
                float p4 = sc[2*kp+1][0], p5 = sc[2*kp+1][1];
                float p6 = sc[2*kp+1][2], p7 = sc[2*kp+1][3];
                ph[0] = pack_bf16x2(p0, p1);
                ph[1] = pack_bf16x2(p2, p3);
                ph[2] = pack_bf16x2(p4, p5);
                ph[3] = pack_bf16x2(p6, p7);
                __nv_bfloat162* hp;
                hp = reinterpret_cast<__nv_bfloat162*>(&ph[0]);
                pl[0] = pack_bf16x2(p0 - __bfloat162float(hp->x), p1 - __bfloat162float(hp->y));
                hp = reinterpret_cast<__nv_bfloat162*>(&ph[1]);
                pl[1] = pack_bf16x2(p2 - __bfloat162float(hp->x), p3 - __bfloat162float(hp->y));
                hp = reinterpret_cast<__nv_bfloat162*>(&ph[2]);
                pl[2] = pack_bf16x2(p4 - __bfloat162float(hp->x), p5 - __bfloat162float(hp->y));
                hp = reinterpret_cast<__nv_bfloat162*>(&ph[3]);
                pl[3] = pack_bf16x2(p6 - __bfloat162float(hp->x), p7 - __bfloat162float(hp->y));
            }
#pragma unroll
            for (int ng = 0; ng < 8; ng++) {
                int ch = ng >> 2;
                uint32_t n0 = (uint32_t)((ng & 3)*16) + ((lane >> 4) << 3);
                uint32_t krow = (uint32_t)(kp*16) + (lane & 15);
                uint32_t off = SWZ(krow*128u + n0*2u);
                uint32_t vh[4], vl[4];
                ldmatrix_x4_trans(vh, sb + FL_VH + ch*8192 + off);
                ldmatrix_x4_trans(vl, sb + FL_VL + ch*8192 + off);
                mma_bf16(oc[ng*2],   ph, vh[0], vh[1]);
                mma_bf16(oc[ng*2],   ph, vl[0], vl[1]);
                mma_bf16(oc[ng*2],   pl, vh[0], vh[1]);
                mma_bf16(oc[ng*2+1], ph, vh[2], vh[3]);
                mma_bf16(oc[ng*2+1], ph, vl[2], vl[3]);
                mma_bf16(oc[ng*2+1], pl, vh[2], vh[3]);
            }
        }
    }

    float inv0 = 1.f / l0, inv1 = 1.f / l1;
    int row0 = bb + s0 + wrow + (lane >> 2);
    int row1 = row0 + 8;
#pragma unroll
    for (int nt = 0; nt < 16; nt++) {
        int col = h*128 + nt*8 + (lane & 3)*2;
        float o0 = oc[nt][0]*inv0, o1 = oc[nt][1]*inv0;
        float o2 = oc[nt][2]*inv1, o3 = oc[nt][3]*inv1;
        uint32_t h0 = pack_bf16x2(o0, o1);
        __nv_bfloat162 hv0 = *reinterpret_cast<__nv_bfloat162*>(&h0);
        uint32_t l0p = pack_bf16x2(o0 - __bfloat162float(hv0.x), o1 - __bfloat162float(hv0.y));
        uint32_t h1 = pack_bf16x2(o2, o3);
        __nv_bfloat162 hv1 = *reinterpret_cast<__nv_bfloat162*>(&h1);
        uint32_t l1p = pack_bf16x2(o2 - __bfloat162float(hv1.x), o3 - __bfloat162float(hv1.y));
        *reinterpret_cast<uint32_t*>(atth + (size_t)row0*2048 + col) = h0;
        *reinterpret_cast<uint32_t*>(attl + (size_t)row0*2048 + col) = l0p;
        *reinterpret_cast<uint32_t*>(atth + (size_t)row1*2048 + col) = h1;
        *reinterpret_cast<uint32_t*>(attl + (size_t)row1*2048 + col) = l1p;
    }
}

// ---------------- host launcher ----------------
extern "C" void kernel_launch(void* const* d_in, const int* in_sizes, int n_in,
                              void* d_out, int out_size)
{
    const float* x      = (const float*)d_in[0];
    const float* wqa    = (const float*)d_in[1];
    const float* wqa_b  = (const float*)d_in[2];
    const float* qnw    = (const float*)d_in[3];
    const float* wqb    = (const float*)d_in[4];
    const float* wqb_b  = (const float*)d_in[5];
    const float* wkva   = (const float*)d_in[6];
    const float* wkva_b = (const float*)d_in[7];
    const float* kvnw   = (const float*)d_in[8];
    const float* wkvb   = (const float*)d_in[9];
    const float* wkvb_b = (const float*)d_in[10];
    const float* wo     = (const float*)d_in[11];
    const float* wo_b   = (const float*)d_in[12];
    float* out = (float*)d_out;

    float *qa, *qbp, *kva, *kvb;
    cudaGetSymbolAddress((void**)&qa,  g_qa);
    cudaGetSymbolAddress((void**)&qbp, g_qb);
    cudaGetSymbolAddress((void**)&kva, g_kva);
    cudaGetSymbolAddress((void**)&kvb, g_kvb);
    __nv_bfloat16 *xh,*xl,*qah,*qal,*kvch,*kvcl,*atth,*attl;
    __nv_bfloat16 *wqah,*wqal,*wqbh,*wqbl,*wkvah,*wkval,*wkvbh,*wkvbl,*woh,*wol;
    __nv_bfloat16 *kfh,*kfl,*vfh,*vfl;
    cudaGetSymbolAddress((void**)&xh, g_xh);   cudaGetSymbolAddress((void**)&xl, g_xl);
    cudaGetSymbolAddress((void**)&qah, g_qah); cudaGetSymbolAddress((void**)&qal, g_qal);
    cudaGetSymbolAddress((void**)&kvch, g_kvch); cudaGetSymbolAddress((void**)&kvcl, g_kvcl);
    cudaGetSymbolAddress((void**)&atth, g_atth); cudaGetSymbolAddress((void**)&attl, g_attl);
    cudaGetSymbolAddress((void**)&wqah, g_wqah); cudaGetSymbolAddress((void**)&wqal, g_wqal);
    cudaGetSymbolAddress((void**)&wqbh, g_wqbh); cudaGetSymbolAddress((void**)&wqbl, g_wqbl);
    cudaGetSymbolAddress((void**)&wkvah, g_wkvah); cudaGetSymbolAddress((void**)&wkval, g_wkval);
    cudaGetSymbolAddress((void**)&wkvbh, g_wkvbh); cudaGetSymbolAddress((void**)&wkvbl, g_wkvbl);
    cudaGetSymbolAddress((void**)&woh, g_woh); cudaGetSymbolAddress((void**)&wol, g_wol);
    cudaGetSymbolAddress((void**)&kfh, g_kfh); cudaGetSymbolAddress((void**)&kfl, g_kfl);
    cudaGetSymbolAddress((void**)&vfh, g_vfh); cudaGetSymbolAddress((void**)&vfl, g_vfl);

    cudaFuncSetAttribute(flash_mma, cudaFuncAttributeMaxDynamicSharedMemorySize, FL_SMEM + 128);
    cudaFuncSetAttribute(gemm_bf, cudaFuncAttributeMaxDynamicSharedMemorySize, GB_SMEM);

    dim3 t256(256);

    cvt_hilo<<<(QLORA*DIMX)/1024, t256>>>(wqa, wqah, wqal, QLORA*DIMX);
    cvt_hilo<<<(3072*QLORA)/1024, t256>>>(wqb, wqbh, wqbl, 3072*QLORA);
    cvt_hilo<<<(576*DIMX)/1024, t256>>>(wkva, wkvah, wkval, 576*DIMX);
    cvt_hilo<<<(4096*KVLORA)/1024, t256>>>(wkvb, wkvbh, wkvbl, 4096*KVLORA);
    cvt_hilo<<<(DIMX*2048)/1024, t256>>>(wo, woh, wol, DIMX*2048);
    cvt_hilo<<<(ROWS*DIMX)/1024, t256>>>(x, xh, xl, ROWS*DIMX);

    gemm_bf<<<dim3(QLORA/256, ROWS/128), t256, GB_SMEM>>>(xh, xl, DIMX, wqah, wqal, DIMX, wqa_b, qa, QLORA, QLORA, DIMX);
    rmsnorm_hilo<<<ROWS, t256>>>(qa, qah, qal, qnw, QLORA, QLORA, QLORA);
    gemm_bf<<<dim3(3072/256, ROWS/128), t256, GB_SMEM>>>(qah, qal, QLORA, wqbh, wqbl, QLORA, wqb_b, qbp, 3072, 3072, QLORA);
    gemm_bf<<<dim3((576+255)/256, ROWS/128), t256, GB_SMEM>>>(xh, xl, DIMX, wkvah, wkval, DIMX, wkva_b, kva, 576, 576, DIMX);
    rope_kernel<<<ROWS, t256>>>(qbp, kva);
    rmsnorm_hilo<<<ROWS, t256>>>(kva, kvch, kvcl, kvnw, KVLORA, 576, KVLORA);
    gemm_bf<<<dim3(4096/256, ROWS/128), t256, GB_SMEM>>>(kvch, kvcl, KVLORA, wkvbh, wkvbl, KVLORA, wkvb_b, kvb, 4096, 4096, KVLORA);
    cvt_kv<<<ROWS, t256>>>(kvb, kva, kfh, kfl, vfh, vfl);
    flash_mma<<<dim3(SEQL/128, NHEADS, BSZ), t256, FL_SMEM + 128>>>(qbp, kfh, kfl, vfh, vfl, atth, attl);
    gemm_bf<<<dim3(2048/256, ROWS/128), t256, GB_SMEM>>>(atth, attl, 2048, woh, wol, 2048, wo_b, out, 2048, 2048, DIMX);
}

// round 8
// speedup vs baseline: 1.0145x; 1.0145x over previous
#include <cuda_runtime.h>
#include <cuda_bf16.h>
#include <cstdint>
#include <math.h>

#define SEQL   2048
#define BSZ    2
#define ROWS   (BSZ*SEQL)          // 4096
#define DIMX   2048
#define QLORA  1536
#define KVLORA 512
#define NHEADS 16
#define QKHD   192
#define NOPE_D 128
#define ROPE_D 64
#define VHD    128

// ---------------- scratch (static device globals; no allocation) ----------------
__device__ float g_qa [ROWS*QLORA];
__device__ float g_qb [ROWS*(NHEADS*QKHD)];
__device__ float g_kva[ROWS*(KVLORA+ROPE_D)];
__device__ float g_kvb[ROWS*(NHEADS*(NOPE_D+VHD))];

__device__ __nv_bfloat16 g_xh  [ROWS*DIMX],   g_xl  [ROWS*DIMX];
__device__ __nv_bfloat16 g_qah [ROWS*QLORA],  g_qal [ROWS*QLORA];
__device__ __nv_bfloat16 g_kvch[ROWS*KVLORA], g_kvcl[ROWS*KVLORA];
__device__ __nv_bfloat16 g_atth[ROWS*2048],   g_attl[ROWS*2048];
__device__ __nv_bfloat16 g_wqah[QLORA*DIMX],  g_wqal[QLORA*DIMX];
__device__ __nv_bfloat16 g_wqbh[3072*QLORA],  g_wqbl[3072*QLORA];
__device__ __nv_bfloat16 g_wkvah[576*DIMX],   g_wkval[576*DIMX];
__device__ __nv_bfloat16 g_wkvbh[4096*KVLORA],g_wkvbl[4096*KVLORA];
__device__ __nv_bfloat16 g_woh [DIMX*2048],   g_wol [DIMX*2048];
// head-major bf16 K-full (192, rope folded) and V planes for flash
__device__ __nv_bfloat16 g_kfh[ROWS*NHEADS*QKHD], g_kfl[ROWS*NHEADS*QKHD];
__device__ __nv_bfloat16 g_vfh[ROWS*NHEADS*VHD],  g_vfl[ROWS*NHEADS*VHD];

__device__ __forceinline__ uint32_t smem_to_u32(const void* p) {
    uint32_t a;
    asm("{ .reg .u64 t; cvta.to.shared.u64 t, %1; cvt.u32.u64 %0, t; }" : "=r"(a) : "l"(p));
    return a;
}
#define SWZ(x) ((x) ^ (((x) >> 3) & 0x70))

__device__ __forceinline__ void ldmatrix_x4(uint32_t* r, uint32_t addr) {
    asm volatile("ldmatrix.sync.aligned.m8n8.x4.shared.b16 {%0,%1,%2,%3}, [%4];"
        : "=r"(r[0]), "=r"(r[1]), "=r"(r[2]), "=r"(r[3]) : "r"(addr));
}
__device__ __forceinline__ void ldmatrix_x4_trans(uint32_t* r, uint32_t addr) {
    asm volatile("ldmatrix.sync.aligned.m8n8.x4.trans.shared.b16 {%0,%1,%2,%3}, [%4];"
        : "=r"(r[0]), "=r"(r[1]), "=r"(r[2]), "=r"(r[3]) : "r"(addr));
}
__device__ __forceinline__ void mma_bf16(float* c, const uint32_t* a, uint32_t b0, uint32_t b1) {
    asm volatile(
        "mma.sync.aligned.m16n8k16.row.col.f32.bf16.bf16.f32 "
        "{%0,%1,%2,%3}, {%4,%5,%6,%7}, {%8,%9}, {%0,%1,%2,%3};"
        : "+f"(c[0]), "+f"(c[1]), "+f"(c[2]), "+f"(c[3])
        : "r"(a[0]), "r"(a[1]), "r"(a[2]), "r"(a[3]), "r"(b0), "r"(b1));
}
__device__ __forceinline__ uint32_t pack_bf16x2(float lo, float hi) {
    __nv_bfloat162 h = __floats2bfloat162_rn(lo, hi);
    return *reinterpret_cast<uint32_t*>(&h);
}
__device__ __forceinline__ void cp_async16(uint32_t dst, const void* src) {
    asm volatile("cp.async.cg.shared.global [%0], [%1], 16;" :: "r"(dst), "l"(src));
}
#define CP_COMMIT() asm volatile("cp.async.commit_group;" ::: "memory")
#define CP_WAIT1()  asm volatile("cp.async.wait_group 1;" ::: "memory")
#define CP_WAIT0()  asm volatile("cp.async.wait_group 0;" ::: "memory")

// ---------------- fp32 -> bf16 hi/lo planar converter ----------------
__global__ __launch_bounds__(256)
void cvt_hilo(const float* __restrict__ s, __nv_bfloat16* __restrict__ hi,
              __nv_bfloat16* __restrict__ lo, int n)
{
    int i = (blockIdx.x * 256 + threadIdx.x) * 4;
    if (i >= n) return;
    float4 v = *reinterpret_cast<const float4*>(s + i);
    __nv_bfloat162 h01 = __floats2bfloat162_rn(v.x, v.y);
    __nv_bfloat162 h23 = __floats2bfloat162_rn(v.z, v.w);
    __nv_bfloat162 l01 = __floats2bfloat162_rn(v.x - __bfloat162float(h01.x),
                                               v.y - __bfloat162float(h01.y));
    __nv_bfloat162 l23 = __floats2bfloat162_rn(v.z - __bfloat162float(h23.x),
                                               v.w - __bfloat162float(h23.y));
    *reinterpret_cast<uint2*>(hi + i) =
        make_uint2(*reinterpret_cast<uint32_t*>(&h01), *reinterpret_cast<uint32_t*>(&h23));
    *reinterpret_cast<uint2*>(lo + i) =
        make_uint2(*reinterpret_cast<uint32_t*>(&l01), *reinterpret_cast<uint32_t*>(&l23));
}

// ---------------- build head-major K-full / V bf16 hi/lo for flash ----------------
__global__ __launch_bounds__(256)
void cvt_kv(const float* __restrict__ kvb, const float* __restrict__ kva,
            __nv_bfloat16* __restrict__ kfh, __nv_bfloat16* __restrict__ kfl,
            __nv_bfloat16* __restrict__ vfh, __nv_bfloat16* __restrict__ vfl)
{
    int row = blockIdx.x;               // 0..4095
    for (int c = threadIdx.x; c < 1280; c += 256) {
        float4 v;
        __nv_bfloat16 *dh, *dl;
        if (c < 512) {
            int h = c >> 5, d = (c & 31) * 4;
            v = *reinterpret_cast<const float4*>(kvb + (size_t)row*4096 + h*256 + d);
            dh = kfh + ((size_t)row*NHEADS + h)*QKHD + d;
            dl = kfl + ((size_t)row*NHEADS + h)*QKHD + d;
        } else if (c < 768) {
            int cc = c - 512;
            int h = cc >> 4, d2 = (cc & 15) * 4;
            v = *reinterpret_cast<const float4*>(kva + (size_t)row*576 + 512 + d2);
            dh = kfh + ((size_t)row*NHEADS + h)*QKHD + 128 + d2;
            dl = kfl + ((size_t)row*NHEADS + h)*QKHD + 128 + d2;
        } else {
            int cc = c - 768;
            int h = cc >> 5, d = (cc & 31) * 4;
            v = *reinterpret_cast<const float4*>(kvb + (size_t)row*4096 + h*256 + 128 + d);
            dh = vfh + ((size_t)row*NHEADS + h)*VHD + d;
            dl = vfl + ((size_t)row*NHEADS + h)*VHD + d;
        }
        __nv_bfloat162 h01 = __floats2bfloat162_rn(v.x, v.y);
        __nv_bfloat162 h23 = __floats2bfloat162_rn(v.z, v.w);
        __nv_bfloat162 l01 = __floats2bfloat162_rn(v.x - __bfloat162float(h01.x),
                                                   v.y - __bfloat162float(h01.y));
        __nv_bfloat162 l23 = __floats2bfloat162_rn(v.z - __bfloat162float(h23.x),
                                                   v.w - __bfloat162float(h23.y));
        *reinterpret_cast<uint2*>(dh) =
            make_uint2(*reinterpret_cast<uint32_t*>(&h01), *reinterpret_cast<uint32_t*>(&h23));
        *reinterpret_cast<uint2*>(dl) =
            make_uint2(*reinterpret_cast<uint32_t*>(&l01), *reinterpret_cast<uint32_t*>(&l23));
    }
}

// ============ cp.async 3-stage split-bf16 HMMA GEMM, CTA 128x128 (R5 proven) ============
// C[M,N] = (Ah+Al)[M,K] @ (Bh+Bl)[N,K]^T + bias  (3 products)
// 8 warps 4M x 2N, warp tile 32x64, K-tile 64. Stage = Ah|Al|Bh|Bl 16KB each = 64KB, 3 stages.
#define GB_STAGE 65536
#define GB_SMEM  (3*GB_STAGE + 128)

__global__ __launch_bounds__(256, 1)
void gemm_bf(const __nv_bfloat16* __restrict__ Ah, const __nv_bfloat16* __restrict__ Al, int lda,
             const __nv_bfloat16* __restrict__ Bh, const __nv_bfloat16* __restrict__ Bl, int ldw,
             const float* __restrict__ bias,
             float* __restrict__ C, int ldc,
             int Nn, int K)
{
    extern __shared__ char smraw[];
    uint32_t sb0 = smem_to_u32(smraw);
    uint32_t sb = (sb0 + 127u) & ~127u;

    const int tid  = threadIdx.x;
    const int lane = tid & 31;
    const int wid  = tid >> 5;
    const int bm = blockIdx.y * 128;
    const int bn = blockIdx.x * 128;
    const int wm = (wid & 3) * 32;
    const int wn = (wid >> 2) * 64;
    const int nk = K >> 6;

    float acc[2][8][4];
#pragma unroll
    for (int mt = 0; mt < 2; mt++)
#pragma unroll
        for (int nt = 0; nt < 8; nt++)
#pragma unroll
            for (int q = 0; q < 4; q++) acc[mt][nt][q] = 0.f;

    // plane 0=Ah 1=Al 2=Bh 3=Bl; idx within plane = (i&3)*256 + tid
#define GB_ISSUE(kt_) do {                                                      \
        const uint32_t stb = sb + (uint32_t)((kt_) % 3) * GB_STAGE;             \
        const int k0_ = (kt_) << 6;                                             \
        _Pragma("unroll")                                                       \
        for (int i = 0; i < 16; i++) {                                          \
            const int plane = i >> 2;                                           \
            const int idx = ((i & 3) << 8) + tid;                               \
            const int r = idx >> 3;                                             \
            const int c = idx & 7;                                              \
            uint32_t dst = stb + (uint32_t)plane*16384u                         \
                         + SWZ((uint32_t)(r*128 + c*16));                       \
            const __nv_bfloat16* srcp;                                          \
            if (plane == 0)      srcp = Ah + (size_t)(bm + r)*lda + k0_ + c*8;  \
            else if (plane == 1) srcp = Al + (size_t)(bm + r)*lda + k0_ + c*8;  \
            else {                                                              \
                int rr = bn + r; if (rr >= Nn) rr = Nn - 1;                     \
                srcp = (plane == 2 ? Bh : Bl) + (size_t)rr*ldw + k0_ + c*8;     \
            }                                                                   \
            cp_async16(dst, srcp);                                              \
        }                                                                       \
    } while (0)

    GB_ISSUE(0); CP_COMMIT();
    if (nk > 1) { GB_ISSUE(1); }
    CP_COMMIT();

    for (int kt = 0; kt < nk; kt++) {
        CP_WAIT1();
        __syncthreads();

        const uint32_t baseA = sb + (uint32_t)(kt % 3) * GB_STAGE;
        const uint32_t baseB = baseA + 32768u;
#pragma unroll
        for (int k16 = 0; k16 < 4; k16++) {
            uint32_t ah[2][4], al[2][4];
#pragma unroll
            for (int mt = 0; mt < 2; mt++) {
                uint32_t row = wm + mt*16 + (lane & 15);
                uint32_t off = SWZ(row*128u + (uint32_t)(k16*32) + ((lane >> 4) << 4));
                ldmatrix_x4(ah[mt], baseA + off);
                ldmatrix_x4(al[mt], baseA + 16384u + off);
            }
            uint32_t bh[16], bl[16];
#pragma unroll
            for (int ng = 0; ng < 4; ng++) {
                uint32_t nrow = wn + ng*16 + ((lane >> 4) << 3) + (lane & 7);
                uint32_t off = SWZ(nrow*128u + (uint32_t)(k16*32) + (((lane >> 3) & 1) << 4));
                ldmatrix_x4(&bh[ng*4], baseB + off);
                ldmatrix_x4(&bl[ng*4], baseB + 16384u + off);
            }
#pragma unroll
            for (int mt = 0; mt < 2; mt++)
#pragma unroll
                for (int nt = 0; nt < 8; nt++) {
                    mma_bf16(acc[mt][nt], ah[mt], bh[nt*2], bh[nt*2+1]);
                    mma_bf16(acc[mt][nt], ah[mt], bl[nt*2], bl[nt*2+1]);
                    mma_bf16(acc[mt][nt], al[mt], bh[nt*2], bh[nt*2+1]);
                }
        }
        __syncthreads();
        if (kt + 2 < nk) { GB_ISSUE(kt + 2); }
        CP_COMMIT();
    }

    // ---- epilogue ----
#pragma unroll
    for (int nt = 0; nt < 8; nt++) {
        int col = bn + wn + nt*8 + (lane & 3)*2;
        if (col >= Nn) continue;
        float bx = bias[col], by = bias[col+1];
#pragma unroll
        for (int mt = 0; mt < 2; mt++) {
            int row = bm + wm + mt*16 + (lane >> 2);
            *reinterpret_cast<float2*>(C + (size_t)row*ldc + col) =
                make_float2(acc[mt][nt][0] + bx, acc[mt][nt][1] + by);
            *reinterpret_cast<float2*>(C + (size_t)(row+8)*ldc + col) =
                make_float2(acc[mt][nt][2] + bx, acc[mt][nt][3] + by);
        }
    }
#undef GB_ISSUE
}

// ---------------- RMSNorm -> bf16 hi/lo planar ----------------
__global__ __launch_bounds__(256)
void rmsnorm_hilo(const float* __restrict__ src,
                  __nv_bfloat16* __restrict__ hi, __nv_bfloat16* __restrict__ lo,
                  const float* __restrict__ w, int width, int sstride, int dstride)
{
    int row = blockIdx.x;
    const float* s = src + (size_t)row * sstride;

    float ss = 0.f;
    for (int c = threadIdx.x; c < width; c += blockDim.x) { float v = s[c]; ss += v*v; }

    __shared__ float red[8];
#pragma unroll
    for (int off = 16; off; off >>= 1) ss += __shfl_xor_sync(0xffffffffu, ss, off);
    int warp = threadIdx.x >> 5;
    if ((threadIdx.x & 31) == 0) red[warp] = ss;
    __syncthreads();
    if (warp == 0) {
        float v = (threadIdx.x < 8) ? red[threadIdx.x] : 0.f;
#pragma unroll
        for (int off = 4; off; off >>= 1) v += __shfl_xor_sync(0xffffffffu, v, off);
        if (threadIdx.x == 0) red[0] = v;
    }
    __syncthreads();
    float scale = rsqrtf(red[0] / (float)width + 1e-6f);
    __nv_bfloat16* dh = hi + (size_t)row * dstride;
    __nv_bfloat16* dl = lo + (size_t)row * dstride;
    for (int c = threadIdx.x; c < width; c += blockDim.x) {
        float v = s[c] * scale * w[c];
        __nv_bfloat16 hv = __float2bfloat16_rn(v);
        dh[c] = hv;
        dl[c] = __float2bfloat16_rn(v - __bfloat162float(hv));
    }
}

// ---------------- RoPE ----------------
__global__ __launch_bounds__(256)
void rope_kernel(float* __restrict__ qb, float* __restrict__ kva)
{
    int row = blockIdx.x;
    int s = row & (SEQL - 1);
    for (int p = threadIdx.x; p < 544; p += blockDim.x) {
        int d = p & 31;
        float ang = (float)s * powf(10000.f, -(float)d * (1.f/32.f));
        float sn, c;
        sincosf(ang, &sn, &c);
        float* base;
        if (p < 512) {
            int hh = p >> 5;
            base = qb + (size_t)row*(NHEADS*QKHD) + hh*QKHD + NOPE_D;
        } else {
            base = kva + (size_t)row*(KVLORA+ROPE_D) + KVLORA;
        }
        float x1 = base[d], x2 = base[d+32];
        base[d]    = x1*c - x2*sn;
        base[d+32] = x2*c + x1*sn;
    }
}

// ============ Flash attention via mma.sync (split-bf16), cp.async K/V ============
#define FL_QH 0
#define FL_QL 49152
#define FL_KH 98304
#define FL_KL 122880
#define FL_VH 147456
#define FL_VL 163840
#define FL_SMEM 180224

__global__ __launch_bounds__(256, 1)
void flash_mma(const float* __restrict__ qb,
               const __nv_bfloat16* __restrict__ kfh, const __nv_bfloat16* __restrict__ kfl,
               const __nv_bfloat16* __restrict__ vfh, const __nv_bfloat16* __restrict__ vfl,
               __nv_bfloat16* __restrict__ atth,
               __nv_bfloat16* __restrict__ attl)
{
    extern __shared__ char smraw[];
    uint32_t sb0 = smem_to_u32(smraw);
    uint32_t sb = (sb0 + 127u) & ~127u;
    char* smp = smraw + (sb - sb0);

    const int qt = blockIdx.x;
    const int h  = blockIdx.y;
    const int b  = blockIdx.z;
    const int s0 = qt * 128;
    const int bb = b * SEQL;
    const int tid  = threadIdx.x;
    const int lane = tid & 31;
    const int wid  = tid >> 5;
    const int wrow = wid * 16;
    const float scale = 0.07216878364870323f;

    // ---- load Q (128 x 192), prescaled, hi/lo (once per block) ----
#pragma unroll
    for (int i = 0; i < 24; i++) {
        int idx = tid + i*256;
        int row = idx / 48;
        int d = (idx - row*48) * 4;
        float4 v = *reinterpret_cast<const float4*>(
            qb + (size_t)(bb + s0 + row)*3072 + h*192 + d);
        v.x *= scale; v.y *= scale; v.z *= scale; v.w *= scale;
        int ch = d >> 6, dc = d & 63;
        uint32_t off = SWZ((uint32_t)(row*128 + dc*2));
        __nv_bfloat162 h01 = __floats2bfloat162_rn(v.x, v.y);
        __nv_bfloat162 h23 = __floats2bfloat162_rn(v.z, v.w);
        __nv_bfloat162 l01 = __floats2bfloat162_rn(v.x - __bfloat162float(h01.x),
                                                   v.y - __bfloat162float(h01.y));
        __nv_bfloat162 l23 = __floats2bfloat162_rn(v.z - __bfloat162float(h23.x),
                                                   v.w - __bfloat162float(h23.y));
        *reinterpret_cast<uint2*>(smp + FL_QH + ch*16384 + off) =
            make_uint2(*reinterpret_cast<uint32_t*>(&h01), *reinterpret_cast<uint32_t*>(&h23));
        *reinterpret_cast<uint2*>(smp + FL_QL + ch*16384 + off) =
            make_uint2(*reinterpret_cast<uint32_t*>(&l01), *reinterpret_cast<uint32_t*>(&l23));
    }

    float oc[16][4];
#pragma unroll
    for (int nt = 0; nt < 16; nt++)
#pragma unroll
        for (int q = 0; q < 4; q++) oc[nt][q] = 0.f;
    float m0 = -1e30f, m1 = -1e30f, l0 = 0.f, l1 = 0.f;

    const int rg0 = s0 + wrow + (lane >> 2);
    const int rg1 = rg0 + 8;
    const int nkt = 2*qt + 2;

    for (int kt = 0; kt < nkt; kt++) {
        if (kt > 0) __syncthreads();
        const int ks0 = kt * 64;

        // ---- K tiles: hi/lo, 64 rows x 24 16B-chunks each ----
#pragma unroll
        for (int i = 0; i < 12; i++) {
            int idx = tid + i*256;
            int cidx = idx;
            const __nv_bfloat16* src;
            uint32_t base;
            if (cidx < 1536) { src = kfh; base = (uint32_t)FL_KH; }
            else             { src = kfl; base = (uint32_t)FL_KL; cidx -= 1536; }
            int row = cidx / 24;
            int c = cidx - row*24;
            int ch = c >> 3;
            int dc8 = (c & 7) * 8;
            uint32_t dst = sb + base + ch*8192u + SWZ((uint32_t)(row*128 + dc8*2));
            cp_async16(dst, src + ((size_t)(bb + ks0 + row)*NHEADS + h)*QKHD + ch*64 + dc8);
        }
        // ---- V tiles: hi/lo, 64 rows x 16 chunks each ----
#pragma unroll
        for (int i = 0; i < 8; i++) {
            int idx = tid + i*256;
            int cidx = idx;
            const __nv_bfloat16* src;
            uint32_t base;
            if (cidx < 1024) { src = vfh; base = (uint32_t)FL_VH; }
            else             { src = vfl; base = (uint32_t)FL_VL; cidx -= 1024; }
            int row = cidx >> 4;
            int c = cidx & 15;
            int ch = c >> 3;
            int dc8 = (c & 7) * 8;
            uint32_t dst = sb + base + ch*8192u + SWZ((uint32_t)(row*128 + dc8*2));
            cp_async16(dst, src + ((size_t)(bb + ks0 + row)*NHEADS + h)*VHD + ch*64 + dc8);
        }
        CP_COMMIT();
        CP_WAIT0();
        __syncthreads();

        if (ks0 > s0 + wrow + 15) continue;

        float sc[8][4];
#pragma unroll
        for (int nt = 0; nt < 8; nt++)
#pragma unroll
            for (int q = 0; q < 4; q++) sc[nt][q] = 0.f;

#pragma unroll
        for (int ks = 0; ks < 12; ks++) {
            int ch = ks >> 2;
            uint32_t kb = (uint32_t)((ks & 3) * 32);
            uint32_t ah[4], al[4];
            {
                uint32_t row = wrow + (lane & 15);
                uint32_t off = SWZ(row*128u + kb + ((lane >> 4) << 4));
                ldmatrix_x4(ah, sb + FL_QH + ch*16384 + off);
                ldmatrix_x4(al, sb + FL_QL + ch*16384 + off);
            }
            uint32_t bh[16], bl[16];
#pragma unroll
            for (int ng = 0; ng < 4; ng++) {
                uint32_t nrow = ng*16 + ((lane >> 4) << 3) + (lane & 7);
                uint32_t off = SWZ(nrow*128u + kb + (((lane >> 3) & 1) << 4));
                ldmatrix_x4(&bh[ng*4], sb + FL_KH + ch*8192 + off);
                ldmatrix_x4(&bl[ng*4], sb + FL_KL + ch*8192 + off);
            }
#pragma unroll
            for (int nt = 0; nt < 8; nt++) {
                mma_bf16(sc[nt], ah, bh[nt*2], bh[nt*2+1]);
                mma_bf16(sc[nt], ah, bl[nt*2], bl[nt*2+1]);
                mma_bf16(sc[nt], al, bh[nt*2], bh[nt*2+1]);
            }
        }

        if (ks0 + 63 > s0 + wrow) {
#pragma unroll
            for (int nt = 0; nt < 8; nt++) {
                int colg = ks0 + nt*8 + (lane & 3)*2;
                if (colg     > rg0) sc[nt][0] = -1e30f;
                if (colg + 1 > rg0) sc[nt][1] = -1e30f;
                if (colg     > rg1) sc[nt][2] = -1e30f;
                if (colg + 1 > rg1) sc[nt][3] = -1e30f;
            }
        }

        float mx0 = -1e30f, mx1 = -1e30f;
#pragma unroll
        for (int nt = 0; nt < 8; nt++) {
            mx0 = fmaxf(mx0, fmaxf(sc[nt][0], sc[nt][1]));
            mx1 = fmaxf(mx1, fmaxf(sc[nt][2], sc[nt][3]));
        }
        mx0 = fmaxf(mx0, __shfl_xor_sync(0xffffffffu, mx0, 1));
        mx0 = fmaxf(mx0, __shfl_xor_sync(0xffffffffu, mx0, 2));
        mx1 = fmaxf(mx1, __shfl_xor_sync(0xffffffffu, mx1, 1));
        mx1 = fmaxf(mx1, __shfl_xor_sync(0xffffffffu, mx1, 2));
        float mn0 = fmaxf(m0, mx0), mn1 = fmaxf(m1, mx1);
        float a0 = __expf(m0 - mn0), a1 = __expf(m1 - mn1);
        m0 = mn0; m1 = mn1;
        float rs0 = 0.f, rs1 = 0.f;
#pragma unroll
        for (int nt = 0; nt < 8; nt++) {
            sc[nt][0] = __expf(sc[nt][0] - mn0); rs0 += sc[nt][0];
            sc[nt][1] = __expf(sc[nt][1] - mn0); rs0 += sc[nt][1];
            sc[nt][2] = __expf(sc[nt][2] - mn1); rs1 += sc[nt][2];
            sc[nt][3] = __expf(sc[nt][3] - mn1); rs1 += sc[nt][3];
        }
        rs0 += __shfl_xor_sync(0xffffffffu, rs0, 1);
        rs0 += __shfl_xor_sync(0xffffffffu, rs0, 2);
        rs1 += __shfl_xor_sync(0xffffffffu, rs1, 1);
        rs1 += __shfl_xor_sync(0xffffffffu, rs1, 2);
        l0 = l0*a0 + rs0;
        l1 = l1*a1 + rs1;
#pragma unroll
        for (int nt = 0; nt < 16; nt++) {
            oc[nt][0] *= a0; oc[nt][1] *= a0;
            oc[nt][2] *= a1; oc[nt][3] *= a1;
        }

#pragma unroll
        for (int kp = 0; kp < 4; kp++) {
            uint32_t ph[4], pl[4];
            {
                float p0 = sc[2*kp][0],  p1 = sc[2*kp][1];
                float p2 = sc[2*kp][2],  p3 = sc[2*kp][3];
                float p4 = sc[2*kp+1][0], p5 = sc[2*kp+1][1];
                float p6 = sc[2*kp+1][2], p7 = sc[2*kp+1][3];
                ph[0] = pack_bf16x2(p0, p1);
                ph[1] = pack_bf16x2(p2, p3);
                ph[2] = pack_bf16x2(p4, p5);
                ph[3] = pack_bf16x2(p6, p7);
                __nv_bfloat162* hp;
                hp = reinterpret_cast<__nv_bfloat162*>(&ph[0]);
                pl[0] = pack_bf16x2(p0 - __bfloat162float(hp->x), p1 - __bfloat162float(hp->y));
                hp = reinterpret_cast<__nv_bfloat162*>(&ph[1]);
                pl[1] = pack_bf16x2(p2 - __bfloat162float(hp->x), p3 - __bfloat162float(hp->y));
                hp = reinterpret_cast<__nv_bfloat162*>(&ph[2]);
                pl[2] = pack_bf16x2(p4 - __bfloat162float(hp->x), p5 - __bfloat162float(hp->y));
                hp = reinterpret_cast<__nv_bfloat162*>(&ph[3]);
                pl[3] = pack_bf16x2(p6 - __bfloat162float(hp->x), p7 - __bfloat162float(hp->y));
            }
#pragma unroll
            for (int ng = 0; ng < 8; ng++) {
                int ch = ng >> 2;
                uint32_t n0 = (uint32_t)((ng & 3)*16) + ((lane >> 4) << 3);
                uint32_t krow = (uint32_t)(kp*16) + (lane & 15);
                uint32_t off = SWZ(krow*128u + n0*2u);
                uint32_t vh[4], vl[4];
                ldmatrix_x4_trans(vh, sb + FL_VH + ch*8192 + off);
                ldmatrix_x4_trans(vl, sb + FL_VL + ch*8192 + off);
                mma_bf16(oc[ng*2],   ph, vh[0], vh[1]);
                mma_bf16(oc[ng*2],   ph, vl[0], vl[1]);
                mma_bf16(oc[ng*2],   pl, vh[0], vh[1]);
                mma_bf16(oc[ng*2+1], ph, vh[2], vh[3]);
                mma_bf16(oc[ng*2+1], ph, vl[2], vl[3]);
                mma_bf16(oc[ng*2+1], pl, vh[2], vh[3]);
            }
        }
    }

    float inv0 = 1.f / l0, inv1 = 1.f / l1;
    int row0 = bb + s0 + wrow + (lane >> 2);
    int row1 = row0 + 8;
#pragma unroll
    for (int nt = 0; nt < 16; nt++) {
        int col = h*128 + nt*8 + (lane & 3)*2;
        float o0 = oc[nt][0]*inv0, o1 = oc[nt][1]*inv0;
        float o2 = oc[nt][2]*inv1, o3 = oc[nt][3]*inv1;
        uint32_t h0 = pack_bf16x2(o0, o1);
        __nv_bfloat162 hv0 = *reinterpret_cast<__nv_bfloat162*>(&h0);
        uint32_t l0p = pack_bf16x2(o0 - __bfloat162float(hv0.x), o1 - __bfloat162float(hv0.y));
        uint32_t h1 = pack_bf16x2(o2, o3);
        __nv_bfloat162 hv1 = *reinterpret_cast<__nv_bfloat162*>(&h1);
        uint32_t l1p = pack_bf16x2(o2 - __bfloat162float(hv1.x), o3 - __bfloat162float(hv1.y));
        *reinterpret_cast<uint32_t*>(atth + (size_t)row0*2048 + col) = h0;
        *reinterpret_cast<uint32_t*>(attl + (size_t)row0*2048 + col) = l0p;
        *reinterpret_cast<uint32_t*>(atth + (size_t)row1*2048 + col) = h1;
        *reinterpret_cast<uint32_t*>(attl + (size_t)row1*2048 + col) = l1p;
    }
}

// ---------------- host launcher ----------------
extern "C" void kernel_launch(void* const* d_in, const int* in_sizes, int n_in,
                              void* d_out, int out_size)
{
    const float* x      = (const float*)d_in[0];
    const float* wqa    = (const float*)d_in[1];
    const float* wqa_b  = (const float*)d_in[2];
    const float* qnw    = (const float*)d_in[3];
    const float* wqb    = (const float*)d_in[4];
    const float* wqb_b  = (const float*)d_in[5];
    const float* wkva   = (const float*)d_in[6];
    const float* wkva_b = (const float*)d_in[7];
    const float* kvnw   = (const float*)d_in[8];
    const float* wkvb   = (const float*)d_in[9];
    const float* wkvb_b = (const float*)d_in[10];
    const float* wo     = (const float*)d_in[11];
    const float* wo_b   = (const float*)d_in[12];
    float* out = (float*)d_out;

    float *qa, *qbp, *kva, *kvb;
    cudaGetSymbolAddress((void**)&qa,  g_qa);
    cudaGetSymbolAddress((void**)&qbp, g_qb);
    cudaGetSymbolAddress((void**)&kva, g_kva);
    cudaGetSymbolAddress((void**)&kvb, g_kvb);
    __nv_bfloat16 *xh,*xl,*qah,*qal,*kvch,*kvcl,*atth,*attl;
    __nv_bfloat16 *wqah,*wqal,*wqbh,*wqbl,*wkvah,*wkval,*wkvbh,*wkvbl,*woh,*wol;
    __nv_bfloat16 *kfh,*kfl,*vfh,*vfl;
    cudaGetSymbolAddress((void**)&xh, g_xh);   cudaGetSymbolAddress((void**)&xl, g_xl);
    cudaGetSymbolAddress((void**)&qah, g_qah); cudaGetSymbolAddress((void**)&qal, g_qal);
    cudaGetSymbolAddress((void**)&kvch, g_kvch); cudaGetSymbolAddress((void**)&kvcl, g_kvcl);
    cudaGetSymbolAddress((void**)&atth, g_atth); cudaGetSymbolAddress((void**)&attl, g_attl);
    cudaGetSymbolAddress((void**)&wqah, g_wqah); cudaGetSymbolAddress((void**)&wqal, g_wqal);
    cudaGetSymbolAddress((void**)&wqbh, g_wqbh); cudaGetSymbolAddress((void**)&wqbl, g_wqbl);
    cudaGetSymbolAddress((void**)&wkvah, g_wkvah); cudaGetSymbolAddress((void**)&wkval, g_wkval);
    cudaGetSymbolAddress((void**)&wkvbh, g_wkvbh); cudaGetSymbolAddress((void**)&wkvbl, g_wkvbl);
    cudaGetSymbolAddress((void**)&woh, g_woh); cudaGetSymbolAddress((void**)&wol, g_wol);
    cudaGetSymbolAddress((void**)&kfh, g_kfh); cudaGetSymbolAddress((void**)&kfl, g_kfl);
    cudaGetSymbolAddress((void**)&vfh, g_vfh); cudaGetSymbolAddress((void**)&vfl, g_vfl);

    cudaFuncSetAttribute(flash_mma, cudaFuncAttributeMaxDynamicSharedMemorySize, FL_SMEM + 128);
    cudaFuncSetAttribute(gemm_bf, cudaFuncAttributeMaxDynamicSharedMemorySize, GB_SMEM);

    dim3 t256(256);

    cvt_hilo<<<(QLORA*DIMX)/1024, t256>>>(wqa, wqah, wqal, QLORA*DIMX);
    cvt_hilo<<<(3072*QLORA)/1024, t256>>>(wqb, wqbh, wqbl, 3072*QLORA);
    cvt_hilo<<<(576*DIMX)/1024, t256>>>(wkva, wkvah, wkval, 576*DIMX);
    cvt_hilo<<<(4096*KVLORA)/1024, t256>>>(wkvb, wkvbh, wkvbl, 4096*KVLORA);
    cvt_hilo<<<(DIMX*2048)/1024, t256>>>(wo, woh, wol, DIMX*2048);
    cvt_hilo<<<(ROWS*DIMX)/1024, t256>>>(x, xh, xl, ROWS*DIMX);

    gemm_bf<<<dim3(QLORA/128, ROWS/128), t256, GB_SMEM>>>(xh, xl, DIMX, wqah, wqal, DIMX, wqa_b, qa, QLORA, QLORA, DIMX);
    rmsnorm_hilo<<<ROWS, t256>>>(qa, qah, qal, qnw, QLORA, QLORA, QLORA);
    gemm_bf<<<dim3(3072/128, ROWS/128), t256, GB_SMEM>>>(qah, qal, QLORA, wqbh, wqbl, QLORA, wqb_b, qbp, 3072, 3072, QLORA);
    gemm_bf<<<dim3((576+127)/128, ROWS/128), t256, GB_SMEM>>>(xh, xl, DIMX, wkvah, wkval, DIMX, wkva_b, kva, 576, 576, DIMX);
    rope_kernel<<<ROWS, t256>>>(qbp, kva);
    rmsnorm_hilo<<<ROWS, t256>>>(kva, kvch, kvcl, kvnw, KVLORA, 576, KVLORA);
    gemm_bf<<<dim3(4096/128, ROWS/128), t256, GB_SMEM>>>(kvch, kvcl, KVLORA, wkvbh, wkvbl, KVLORA, wkvb_b, kvb, 4096, 4096, KVLORA);
    cvt_kv<<<ROWS, t256>>>(kvb, kva, kfh, kfl, vfh, vfl);
    flash_mma<<<dim3(SEQL/128, NHEADS, BSZ), t256, FL_SMEM + 128>>>(qbp, kfh, kfl, vfh, vfl, atth, attl);
    gemm_bf<<<dim3(2048/128, ROWS/128), t256, GB_SMEM>>>(atth, attl, 2048, woh, wol, 2048, wo_b, out, 2048, 2048, DIMX);
}

// round 9
// speedup vs baseline: 1.0281x; 1.0134x over previous
#include <cuda_runtime.h>
#include <cuda_bf16.h>
#include <cstdint>
#include <math.h>

#define SEQL   2048
#define BSZ    2
#define ROWS   (BSZ*SEQL)          // 4096
#define DIMX   2048
#define QLORA  1536
#define KVLORA 512
#define NHEADS 16
#define QKHD   192
#define NOPE_D 128
#define ROPE_D 64
#define VHD    128
#define QKVW   2112                // 1536 q + 512 kv_c + 64 k_pe

// ---------------- scratch (static device globals; no allocation) ----------------
__device__ float g_qkv[ROWS*QKVW];                 // merged q_a | kv_c | k_pe (fp32)
__device__ float g_qb [ROWS*(NHEADS*QKHD)];
__device__ float g_kvb[ROWS*(NHEADS*(NOPE_D+VHD))];
__device__ float g_bqkv[QKVW];

__device__ __nv_bfloat16 g_xh  [ROWS*DIMX],   g_xl  [ROWS*DIMX];
__device__ __nv_bfloat16 g_qah [ROWS*QLORA],  g_qal [ROWS*QLORA];
__device__ __nv_bfloat16 g_kvch[ROWS*KVLORA], g_kvcl[ROWS*KVLORA];
__device__ __nv_bfloat16 g_atth[ROWS*2048],   g_attl[ROWS*2048];
__device__ __nv_bfloat16 g_wqkvh[QKVW*DIMX],  g_wqkvl[QKVW*DIMX];   // wq_a rows 0..1535, wkv_a rows 1536..2111
__device__ __nv_bfloat16 g_wqbh[3072*QLORA],  g_wqbl[3072*QLORA];
__device__ __nv_bfloat16 g_wkvbh[4096*KVLORA],g_wkvbl[4096*KVLORA];
__device__ __nv_bfloat16 g_woh [DIMX*2048],   g_wol [DIMX*2048];
// head-major bf16 K-full (192, rope folded) and V planes for flash
__device__ __nv_bfloat16 g_kfh[ROWS*NHEADS*QKHD], g_kfl[ROWS*NHEADS*QKHD];
__device__ __nv_bfloat16 g_vfh[ROWS*NHEADS*VHD],  g_vfl[ROWS*NHEADS*VHD];

__device__ __forceinline__ uint32_t smem_to_u32(const void* p) {
    uint32_t a;
    asm("{ .reg .u64 t; cvta.to.shared.u64 t, %1; cvt.u32.u64 %0, t; }" : "=r"(a) : "l"(p));
    return a;
}
#define SWZ(x)   ((x) ^ (((x) >> 3) & 0x70))    // 128B-row swizzle (flash)
#define SWZ64(x) ((x) ^ (((x) >> 3) & 0x30))    // 64B-row swizzle (gemm K32)

__device__ __forceinline__ void ldmatrix_x4(uint32_t* r, uint32_t addr) {
    asm volatile("ldmatrix.sync.aligned.m8n8.x4.shared.b16 {%0,%1,%2,%3}, [%4];"
        : "=r"(r[0]), "=r"(r[1]), "=r"(r[2]), "=r"(r[3]) : "r"(addr));
}
__device__ __forceinline__ void ldmatrix_x4_trans(uint32_t* r, uint32_t addr) {
    asm volatile("ldmatrix.sync.aligned.m8n8.x4.trans.shared.b16 {%0,%1,%2,%3}, [%4];"
        : "=r"(r[0]), "=r"(r[1]), "=r"(r[2]), "=r"(r[3]) : "r"(addr));
}
__device__ __forceinline__ void mma_bf16(float* c, const uint32_t* a, uint32_t b0, uint32_t b1) {
    asm volatile(
        "mma.sync.aligned.m16n8k16.row.col.f32.bf16.bf16.f32 "
        "{%0,%1,%2,%3}, {%4,%5,%6,%7}, {%8,%9}, {%0,%1,%2,%3};"
        : "+f"(c[0]), "+f"(c[1]), "+f"(c[2]), "+f"(c[3])
        : "r"(a[0]), "r"(a[1]), "r"(a[2]), "r"(a[3]), "r"(b0), "r"(b1));
}
__device__ __forceinline__ uint32_t pack_bf16x2(float lo, float hi) {
    __nv_bfloat162 h = __floats2bfloat162_rn(lo, hi);
    return *reinterpret_cast<uint32_t*>(&h);
}
__device__ __forceinline__ void cp_async16(uint32_t dst, const void* src) {
    asm volatile("cp.async.cg.shared.global [%0], [%1], 16;" :: "r"(dst), "l"(src));
}
#define CP_COMMIT() asm volatile("cp.async.commit_group;" ::: "memory")
#define CP_WAIT1()  asm volatile("cp.async.wait_group 1;" ::: "memory")
#define CP_WAIT0()  asm volatile("cp.async.wait_group 0;" ::: "memory")

// ---------------- fp32 -> bf16 hi/lo planar converter ----------------
__global__ __launch_bounds__(256)
void cvt_hilo(const float* __restrict__ s, __nv_bfloat16* __restrict__ hi,
              __nv_bfloat16* __restrict__ lo, int n)
{
    int i = (blockIdx.x * 256 + threadIdx.x) * 4;
    if (i >= n) return;
    float4 v = *reinterpret_cast<const float4*>(s + i);
    __nv_bfloat162 h01 = __floats2bfloat162_rn(v.x, v.y);
    __nv_bfloat162 h23 = __floats2bfloat162_rn(v.z, v.w);
    __nv_bfloat162 l01 = __floats2bfloat162_rn(v.x - __bfloat162float(h01.x),
                                               v.y - __bfloat162float(h01.y));
    __nv_bfloat162 l23 = __floats2bfloat162_rn(v.z - __bfloat162float(h23.x),
                                               v.w - __bfloat162float(h23.y));
    *reinterpret_cast<uint2*>(hi + i) =
        make_uint2(*reinterpret_cast<uint32_t*>(&h01), *reinterpret_cast<uint32_t*>(&h23));
    *reinterpret_cast<uint2*>(lo + i) =
        make_uint2(*reinterpret_cast<uint32_t*>(&l01), *reinterpret_cast<uint32_t*>(&l23));
}

// ---------------- combine biases for merged qkv gemm ----------------
__global__ __launch_bounds__(256)
void combine_bias(const float* __restrict__ bq, const float* __restrict__ bkv,
                  float* __restrict__ dst)
{
    int i = blockIdx.x * 256 + threadIdx.x;
    if (i < QKVW) dst[i] = (i < QLORA) ? bq[i] : bkv[i - QLORA];
}

// ---------------- build head-major K-full / V bf16 hi/lo for flash ----------------
__global__ __launch_bounds__(256)
void cvt_kv(const float* __restrict__ kvb, const float* __restrict__ qkv,
            __nv_bfloat16* __restrict__ kfh, __nv_bfloat16* __restrict__ kfl,
            __nv_bfloat16* __restrict__ vfh, __nv_bfloat16* __restrict__ vfl)
{
    int row = blockIdx.x;               // 0..4095
    for (int c = threadIdx.x; c < 1280; c += 256) {
        float4 v;
        __nv_bfloat16 *dh, *dl;
        if (c < 512) {
            int h = c >> 5, d = (c & 31) * 4;
            v = *reinterpret_cast<const float4*>(kvb + (size_t)row*4096 + h*256 + d);
            dh = kfh + ((size_t)row*NHEADS + h)*QKHD + d;
            dl = kfl + ((size_t)row*NHEADS + h)*QKHD + d;
        } else if (c < 768) {
            int cc = c - 512;
            int h = cc >> 4, d2 = (cc & 15) * 4;
            v = *reinterpret_cast<const float4*>(qkv + (size_t)row*QKVW + 2048 + d2);
            dh = kfh + ((size_t)row*NHEADS + h)*QKHD + 128 + d2;
            dl = kfl + ((size_t)row*NHEADS + h)*QKHD + 128 + d2;
        } else {
            int cc = c - 768;
            int h = cc >> 5, d = (cc & 31) * 4;
            v = *reinterpret_cast<const float4*>(kvb + (size_t)row*4096 + h*256 + 128 + d);
            dh = vfh + ((size_t)row*NHEADS + h)*VHD + d;
            dl = vfl + ((size_t)row*NHEADS + h)*VHD + d;
        }
        __nv_bfloat162 h01 = __floats2bfloat162_rn(v.x, v.y);
        __nv_bfloat162 h23 = __floats2bfloat162_rn(v.z, v.w);
        __nv_bfloat162 l01 = __floats2bfloat162_rn(v.x - __bfloat162float(h01.x),
                                                   v.y - __bfloat162float(h01.y));
        __nv_bfloat162 l23 = __floats2bfloat162_rn(v.z - __bfloat162float(h23.x),
                                                   v.w - __bfloat162float(h23.y));
        *reinterpret_cast<uint2*>(dh) =
            make_uint2(*reinterpret_cast<uint32_t*>(&h01), *reinterpret_cast<uint32_t*>(&h23));
        *reinterpret_cast<uint2*>(dl) =
            make_uint2(*reinterpret_cast<uint32_t*>(&l01), *reinterpret_cast<uint32_t*>(&l23));
    }
}

// ============ cp.async 3-stage split-bf16 HMMA GEMM, CTA 128x128, K-tile 32 ============
// 2 CTAs/SM target: stage = Ah|Al|Bh|Bl 8KB each = 32KB, 3 stages = 96KB; regs capped 128.
#define GB_STAGE 32768
#define GB_SMEM  (3*GB_STAGE + 128)

__global__ __launch_bounds__(256, 2)
void gemm_bf(const __nv_bfloat16* __restrict__ Ah, const __nv_bfloat16* __restrict__ Al, int lda,
             const __nv_bfloat16* __restrict__ Bh, const __nv_bfloat16* __restrict__ Bl, int ldw,
             const float* __restrict__ bias,
             float* __restrict__ C, int ldc,
             int Nn, int K)
{
    extern __shared__ char smraw[];
    uint32_t sb0 = smem_to_u32(smraw);
    uint32_t sb = (sb0 + 127u) & ~127u;

    const int tid  = threadIdx.x;
    const int lane = tid & 31;
    const int wid  = tid >> 5;
    const int bm = blockIdx.y * 128;
    const int bn = blockIdx.x * 128;
    const int wm = (wid & 3) * 32;
    const int wn = (wid >> 2) * 64;
    const int nk = K >> 5;              // K-tile 32

    float acc[2][8][4];
#pragma unroll
    for (int mt = 0; mt < 2; mt++)
#pragma unroll
        for (int nt = 0; nt < 8; nt++)
#pragma unroll
            for (int q = 0; q < 4; q++) acc[mt][nt][q] = 0.f;

    // plane 0=Ah 1=Al 2=Bh 3=Bl; each plane: 128 rows x 4 chunks of 16B = 512 chunks
#define GB_ISSUE(kt_) do {                                                      \
        const uint32_t stb = sb + (uint32_t)((kt_) % 3) * GB_STAGE;             \
        const int k0_ = (kt_) << 5;                                             \
        _Pragma("unroll")                                                       \
        for (int i = 0; i < 8; i++) {                                           \
            const int plane = i >> 1;                                           \
            const int idx = ((i & 1) << 8) + tid;                               \
            const int r = idx >> 2;                                             \
            const int c = idx & 3;                                              \
            uint32_t dst = stb + (uint32_t)plane*8192u                          \
                         + SWZ64((uint32_t)(r*64 + c*16));                      \
            const __nv_bfloat16* srcp;                                          \
            if (plane == 0)      srcp = Ah + (size_t)(bm + r)*lda + k0_ + c*8;  \
            else if (plane == 1) srcp = Al + (size_t)(bm + r)*lda + k0_ + c*8;  \
            else {                                                              \
                int rr = bn + r; if (rr >= Nn) rr = Nn - 1;                     \
                srcp = (plane == 2 ? Bh : Bl) + (size_t)rr*ldw + k0_ + c*8;     \
            }                                                                   \
            cp_async16(dst, srcp);                                              \
        }                                                                       \
    } while (0)

    GB_ISSUE(0); CP_COMMIT();
    if (nk > 1) { GB_ISSUE(1); }
    CP_COMMIT();

    for (int kt = 0; kt < nk; kt++) {
        CP_WAIT1();
        __syncthreads();

        const uint32_t baseA = sb + (uint32_t)(kt % 3) * GB_STAGE;
        const uint32_t baseB = baseA + 16384u;
#pragma unroll
        for (int k16 = 0; k16 < 2; k16++) {
            uint32_t ah[2][4], al[2][4];
#pragma unroll
            for (int mt = 0; mt < 2; mt++) {
                uint32_t row = wm + mt*16 + (lane & 15);
                uint32_t off = SWZ64(row*64u + (uint32_t)(k16*32) + ((lane >> 4) << 4));
                ldmatrix_x4(ah[mt], baseA + off);
                ldmatrix_x4(al[mt], baseA + 8192u + off);
            }
#pragma unroll
            for (int ng = 0; ng < 4; ng++) {
                uint32_t bh[4], bl[4];
                uint32_t nrow = wn + ng*16 + ((lane >> 4) << 3) + (lane & 7);
                uint32_t off = SWZ64(nrow*64u + (uint32_t)(k16*32) + (((lane >> 3) & 1) << 4));
                ldmatrix_x4(bh, baseB + off);
                ldmatrix_x4(bl, baseB + 8192u + off);
#pragma unroll
                for (int mt = 0; mt < 2; mt++) {
                    float* a0 = acc[mt][2*ng];
                    float* a1 = acc[mt][2*ng+1];
                    mma_bf16(a0, ah[mt], bh[0], bh[1]);
                    mma_bf16(a0, ah[mt], bl[0], bl[1]);
                    mma_bf16(a0, al[mt], bh[0], bh[1]);
                    mma_bf16(a1, ah[mt], bh[2], bh[3]);
                    mma_bf16(a1, ah[mt], bl[2], bl[3]);
                    mma_bf16(a1, al[mt], bh[2], bh[3]);
                }
            }
        }
        __syncthreads();
        if (kt + 2 < nk) { GB_ISSUE(kt + 2); }
        CP_COMMIT();
    }

    // ---- epilogue ----
#pragma unroll
    for (int nt = 0; nt < 8; nt++) {
        int col = bn + wn + nt*8 + (lane & 3)*2;
        if (col >= Nn) continue;
        float bx = bias[col], by = bias[col+1];
#pragma unroll
        for (int mt = 0; mt < 2; mt++) {
            int row = bm + wm + mt*16 + (lane >> 2);
            *reinterpret_cast<float2*>(C + (size_t)row*ldc + col) =
                make_float2(acc[mt][nt][0] + bx, acc[mt][nt][1] + by);
            *reinterpret_cast<float2*>(C + (size_t)(row+8)*ldc + col) =
                make_float2(acc[mt][nt][2] + bx, acc[mt][nt][3] + by);
        }
    }
#undef GB_ISSUE
}

// ---------------- RMSNorm -> bf16 hi/lo planar ----------------
__global__ __launch_bounds__(256)
void rmsnorm_hilo(const float* __restrict__ src,
                  __nv_bfloat16* __restrict__ hi, __nv_bfloat16* __restrict__ lo,
                  const float* __restrict__ w, int width, int sstride, int dstride)
{
    int row = blockIdx.x;
    const float* s = src + (size_t)row * sstride;

    float ss = 0.f;
    for (int c = threadIdx.x; c < width; c += blockDim.x) { float v = s[c]; ss += v*v; }

    __shared__ float red[8];
#pragma unroll
    for (int off = 16; off; off >>= 1) ss += __shfl_xor_sync(0xffffffffu, ss, off);
    int warp = threadIdx.x >> 5;
    if ((threadIdx.x & 31) == 0) red[warp] = ss;
    __syncthreads();
    if (warp == 0) {
        float v = (threadIdx.x < 8) ? red[threadIdx.x] : 0.f;
#pragma unroll
        for (int off = 4; off; off >>= 1) v += __shfl_xor_sync(0xffffffffu, v, off);
        if (threadIdx.x == 0) red[0] = v;
    }
    __syncthreads();
    float scale = rsqrtf(red[0] / (float)width + 1e-6f);
    __nv_bfloat16* dh = hi + (size_t)row * dstride;
    __nv_bfloat16* dl = lo + (size_t)row * dstride;
    for (int c = threadIdx.x; c < width; c += blockDim.x) {
        float v = s[c] * scale * w[c];
        __nv_bfloat16 hv = __float2bfloat16_rn(v);
        dh[c] = hv;
        dl[c] = __float2bfloat16_rn(v - __bfloat162float(hv));
    }
}

// ---------------- RoPE (qb heads + k_pe cols 2048..2111 of qkv) ----------------
__global__ __launch_bounds__(256)
void rope_kernel(float* __restrict__ qb, float* __restrict__ qkv)
{
    int row = blockIdx.x;
    int s = row & (SEQL - 1);
    for (int p = threadIdx.x; p < 544; p += blockDim.x) {
        int d = p & 31;
        float ang = (float)s * powf(10000.f, -(float)d * (1.f/32.f));
        float sn, c;
        sincosf(ang, &sn, &c);
        float* base;
        if (p < 512) {
            int hh = p >> 5;
            base = qb + (size_t)row*(NHEADS*QKHD) + hh*QKHD + NOPE_D;
        } else {
            base = qkv + (size_t)row*QKVW + 2048;
        }
        float x1 = base[d], x2 = base[d+32];
        base[d]    = x1*c - x2*sn;
        base[d+32] = x2*c + x1*sn;
    }
}

// ============ Flash attention via mma.sync (split-bf16), cp.async K/V ============
#define FL_QH 0
#define FL_QL 49152
#define FL_KH 98304
#define FL_KL 122880
#define FL_VH 147456
#define FL_VL 163840
#define FL_SMEM 180224

__global__ __launch_bounds__(256, 1)
void flash_mma(const float* __restrict__ qb,
               const __nv_bfloat16* __restrict__ kfh, const __nv_bfloat16* __restrict__ kfl,
               const __nv_bfloat16* __restrict__ vfh, const __nv_bfloat16* __restrict__ vfl,
               __nv_bfloat16* __restrict__ atth,
               __nv_bfloat16* __restrict__ attl)
{
    extern __shared__ char smraw[];
    uint32_t sb0 = smem_to_u32(smraw);
    uint32_t sb = (sb0 + 127u) & ~127u;
    char* smp = smraw + (sb - sb0);

    const int qt = blockIdx.x;
    const int h  = blockIdx.y;
    const int b  = blockIdx.z;
    const int s0 = qt * 128;
    const int bb = b * SEQL;
    const int tid  = threadIdx.x;
    const int lane = tid & 31;
    const int wid  = tid >> 5;
    const int wrow = wid * 16;
    const float scale = 0.07216878364870323f;

#pragma unroll
    for (int i = 0; i < 24; i++) {
        int idx = tid + i*256;
        int row = idx / 48;
        int d = (idx - row*48) * 4;
        float4 v = *reinterpret_cast<const float4*>(
            qb + (size_t)(bb + s0 + row)*3072 + h*192 + d);
        v.x *= scale; v.y *= scale; v.z *= scale; v.w *= scale;
        int ch = d >> 6, dc = d & 63;
        uint32_t off = SWZ((uint32_t)(row*128 + dc*2));
        __nv_bfloat162 h01 = __floats2bfloat162_rn(v.x, v.y);
        __nv_bfloat162 h23 = __floats2bfloat162_rn(v.z, v.w);
        __nv_bfloat162 l01 = __floats2bfloat162_rn(v.x - __bfloat162float(h01.x),
                                                   v.y - __bfloat162float(h01.y));
        __nv_bfloat162 l23 = __floats2bfloat162_rn(v.z - __bfloat162float(h23.x),
                                                   v.w - __bfloat162float(h23.y));
        *reinterpret_cast<uint2*>(smp + FL_QH + ch*16384 + off) =
            make_uint2(*reinterpret_cast<uint32_t*>(&h01), *reinterpret_cast<uint32_t*>(&h23));
        *reinterpret_cast<uint2*>(smp + FL_QL + ch*16384 + off) =
            make_uint2(*reinterpret_cast<uint32_t*>(&l01), *reinterpret_cast<uint32_t*>(&l23));
    }

    float oc[16][4];
#pragma unroll
    for (int nt = 0; nt < 16; nt++)
#pragma unroll
        for (int q = 0; q < 4; q++) oc[nt][q] = 0.f;
    float m0 = -1e30f, m1 = -1e30f, l0 = 0.f, l1 = 0.f;

    const int rg0 = s0 + wrow + (lane >> 2);
    const int rg1 = rg0 + 8;
    const int nkt = 2*qt + 2;

    for (int kt = 0; kt < nkt; kt++) {
        if (kt > 0) __syncthreads();
        const int ks0 = kt * 64;

#pragma unroll
        for (int i = 0; i < 12; i++) {
            int idx = tid + i*256;
            int cidx = idx;
            const __nv_bfloat16* src;
            uint32_t base;
            if (cidx < 1536) { src = kfh; base = (uint32_t)FL_KH; }
            else             { src = kfl; base = (uint32_t)FL_KL; cidx -= 1536; }
            int row = cidx / 24;
            int c = cidx - row*24;
            int ch = c >> 3;
            int dc8 = (c & 7) * 8;
            uint32_t dst = sb + base + ch*8192u + SWZ((uint32_t)(row*128 + dc8*2));
            cp_async16(dst, src + ((size_t)(bb + ks0 + row)*NHEADS + h)*QKHD + ch*64 + dc8);
        }
#pragma unroll
        for (int i = 0; i < 8; i++) {
            int idx = tid + i*256;
            int cidx = idx;
            const __nv_bfloat16* src;
            uint32_t base;
            if (cidx < 1024) { src = vfh; base = (uint32_t)FL_VH; }
            else             { src = vfl; base = (uint32_t)FL_VL; cidx -= 1024; }
            int row = cidx >> 4;
            int c = cidx & 15;
            int ch = c >> 3;
            int dc8 = (c & 7) * 8;
            uint32_t dst = sb + base + ch*8192u + SWZ((uint32_t)(row*128 + dc8*2));
            cp_async16(dst, src + ((size_t)(bb + ks0 + row)*NHEADS + h)*VHD + ch*64 + dc8);
        }
        CP_COMMIT();
        CP_WAIT0();
        __syncthreads();

        if (ks0 > s0 + wrow + 15) continue;

        float sc[8][4];
#pragma unroll
        for (int nt = 0; nt < 8; nt++)
#pragma unroll
            for (int q = 0; q < 4; q++) sc[nt][q] = 0.f;

#pragma unroll
        for (int ks = 0; ks < 12; ks++) {
            int ch = ks >> 2;
            uint32_t kb = (uint32_t)((ks & 3) * 32);
            uint32_t ah[4], al[4];
            {
                uint32_t row = wrow + (lane & 15);
                uint32_t off = SWZ(row*128u + kb + ((lane >> 4) << 4));
                ldmatrix_x4(ah, sb + FL_QH + ch*16384 + off);
                ldmatrix_x4(al, sb + FL_QL + ch*16384 + off);
            }
            uint32_t bh[16], bl[16];
#pragma unroll
            for (int ng = 0; ng < 4; ng++) {
                uint32_t nrow = ng*16 + ((lane >> 4) << 3) + (lane & 7);
                uint32_t off = SWZ(nrow*128u + kb + (((lane >> 3) & 1) << 4));
                ldmatrix_x4(&bh[ng*4], sb + FL_KH + ch*8192 + off);
                ldmatrix_x4(&bl[ng*4], sb + FL_KL + ch*8192 + off);
            }
#pragma unroll
            for (int nt = 0; nt < 8; nt++) {
                mma_bf16(sc[nt], ah, bh[nt*2], bh[nt*2+1]);
                mma_bf16(sc[nt], ah, bl[nt*2], bl[nt*2+1]);
                mma_bf16(sc[nt], al, bh[nt*2], bh[nt*2+1]);
            }
        }

        if (ks0 + 63 > s0 + wrow) {
#pragma unroll
            for (int nt = 0; nt < 8; nt++) {
                int colg = ks0 + nt*8 + (lane & 3)*2;
                if (colg     > rg0) sc[nt][0] = -1e30f;
                if (colg + 1 > rg0) sc[nt][1] = -1e30f;
                if (colg     > rg1) sc[nt][2] = -1e30f;
                if (colg + 1 > rg1) sc[nt][3] = -1e30f;
            }
        }

        float mx0 = -1e30f, mx1 = -1e30f;
#pragma unroll
        for (int nt = 0; nt < 8; nt++) {
            mx0 = fmaxf(mx0, fmaxf(sc[nt][0], sc[nt][1]));
            mx1 = fmaxf(mx1, fmaxf(sc[nt][2], sc[nt][3]));
        }
        mx0 = fmaxf(mx0, __shfl_xor_sync(0xffffffffu, mx0, 1));
        mx0 = fmaxf(mx0, __shfl_xor_sync(0xffffffffu, mx0, 2));
        mx1 = fmaxf(mx1, __shfl_xor_sync(0xffffffffu, mx1, 1));
        mx1 = fmaxf(mx1, __shfl_xor_sync(0xffffffffu, mx1, 2));
        float mn0 = fmaxf(m0, mx0), mn1 = fmaxf(m1, mx1);
        float a0 = __expf(m0 - mn0), a1 = __expf(m1 - mn1);
        m0 = mn0; m1 = mn1;
        float rs0 = 0.f, rs1 = 0.f;
#pragma unroll
        for (int nt = 0; nt < 8; nt++) {
            sc[nt][0] = __expf(sc[nt][0] - mn0); rs0 += sc[nt][0];
            sc[nt][1] = __expf(sc[nt][1] - mn0); rs0 += sc[nt][1];
            sc[nt][2] = __expf(sc[nt][2] - mn1); rs1 += sc[nt][2];
            sc[nt][3] = __expf(sc[nt][3] - mn1); rs1 += sc[nt][3];
        }
        rs0 += __shfl_xor_sync(0xffffffffu, rs0, 1);
        rs0 += __shfl_xor_sync(0xffffffffu, rs0, 2);
        rs1 += __shfl_xor_sync(0xffffffffu, rs1, 1);
        rs1 += __shfl_xor_sync(0xffffffffu, rs1, 2);
        l0 = l0*a0 + rs0;
        l1 = l1*a1 + rs1;
#pragma unroll
        for (int nt = 0; nt < 16; nt++) {
            oc[nt][0] *= a0; oc[nt][1] *= a0;
            oc[nt][2] *= a1; oc[nt][3] *= a1;
        }

#pragma unroll
        for (int kp = 0; kp < 4; kp++) {
            uint32_t ph[4], pl[4];
            {
                float p0 = sc[2*kp][0],  p1 = sc[2*kp][1];
                float p2 = sc[2*kp][2],  p3 = sc[2*kp][3];
                float p4 = sc[2*kp+1][0], p5 = sc[2*kp+1][1];
                float p6 = sc[2*kp+1][2], p7 = sc[2*kp+1][3];
                ph[0] = pack_bf16x2(p0, p1);
                ph[1] = pack_bf16x2(p2, p3);
                ph[2] = pack_bf16x2(p4, p5);
                ph[3] = pack_bf16x2(p6, p7);
                __nv_bfloat162* hp;
                hp = reinterpret_cast<__nv_bfloat162*>(&ph[0]);
                pl[0] = pack_bf16x2(p0 - __bfloat162float(hp->x), p1 - __bfloat162float(hp->y));
                hp = reinterpret_cast<__nv_bfloat162*>(&ph[1]);
                pl[1] = pack_bf16x2(p2 - __bfloat162float(hp->x), p3 - __bfloat162float(hp->y));
                hp = reinterpret_cast<__nv_bfloat162*>(&ph[2]);
                pl[2] = pack_bf16x2(p4 - __bfloat162float(hp->x), p5 - __bfloat162float(hp->y));
                hp = reinterpret_cast<__nv_bfloat162*>(&ph[3]);
                pl[3] = pack_bf16x2(p6 - __bfloat162float(hp->x), p7 - __bfloat162float(hp->y));
            }
#pragma unroll
            for (int ng = 0; ng < 8; ng++) {
                int ch = ng >> 2;
                uint32_t n0 = (uint32_t)((ng & 3)*16) + ((lane >> 4) << 3);
                uint32_t krow = (uint32_t)(kp*16) + (lane & 15);
                uint32_t off = SWZ(krow*128u + n0*2u);
                uint32_t vh[4], vl[4];
                ldmatrix_x4_trans(vh, sb + FL_VH + ch*8192 + off);
                ldmatrix_x4_trans(vl, sb + FL_VL + ch*8192 + off);
                mma_bf16(oc[ng*2],   ph, vh[0], vh[1]);
                mma_bf16(oc[ng*2],   ph, vl[0], vl[1]);
                mma_bf16(oc[ng*2],   pl, vh[0], vh[1]);
                mma_bf16(oc[ng*2+1], ph, vh[2], vh[3]);
                mma_bf16(oc[ng*2+1], ph, vl[2], vl[3]);
                mma_bf16(oc[ng*2+1], pl, vh[2], vh[3]);
            }
        }
    }

    float inv0 = 1.f / l0, inv1 = 1.f / l1;
    int row0 = bb + s0 + wrow + (lane >> 2);
    int row1 = row0 + 8;
#pragma unroll
    for (int nt = 0; nt < 16; nt++) {
        int col = h*128 + nt*8 + (lane & 3)*2;
        float o0 = oc[nt][0]*inv0, o1 = oc[nt][1]*inv0;
        float o2 = oc[nt][2]*inv1, o3 = oc[nt][3]*inv1;
        uint32_t h0 = pack_bf16x2(o0, o1);
        __nv_bfloat162 hv0 = *reinterpret_cast<__nv_bfloat162*>(&h0);
        uint32_t l0p = pack_bf16x2(o0 - __bfloat162float(hv0.x), o1 - __bfloat162float(hv0.y));
        uint32_t h1 = pack_bf16x2(o2, o3);
        __nv_bfloat162 hv1 = *reinterpret_cast<__nv_bfloat162*>(&h1);
        uint32_t l1p = pack_bf16x2(o2 - __bfloat162float(hv1.x), o3 - __bfloat162float(hv1.y));
        *reinterpret_cast<uint32_t*>(atth + (size_t)row0*2048 + col) = h0;
        *reinterpret_cast<uint32_t*>(attl + (size_t)row0*2048 + col) = l0p;
        *reinterpret_cast<uint32_t*>(atth + (size_t)row1*2048 + col) = h1;
        *reinterpret_cast<uint32_t*>(attl + (size_t)row1*2048 + col) = l1p;
    }
}

// ---------------- host launcher ----------------
extern "C" void kernel_launch(void* const* d_in, const int* in_sizes, int n_in,
                              void* d_out, int out_size)
{
    const float* x      = (const float*)d_in[0];
    const float* wqa    = (const float*)d_in[1];
    const float* wqa_b  = (const float*)d_in[2];
    const float* qnw    = (const float*)d_in[3];
    const float* wqb    = (const float*)d_in[4];
    const float* wqb_b  = (const float*)d_in[5];
    const float* wkva   = (const float*)d_in[6];
    const float* wkva_b = (const float*)d_in[7];
    const float* kvnw   = (const float*)d_in[8];
    const float* wkvb   = (const float*)d_in[9];
    const float* wkvb_b = (const float*)d_in[10];
    const float* wo     = (const float*)d_in[11];
    const float* wo_b   = (const float*)d_in[12];
    float* out = (float*)d_out;

    float *qkv, *qbp, *kvb, *bqkv;
    cudaGetSymbolAddress((void**)&qkv, g_qkv);
    cudaGetSymbolAddress((void**)&qbp, g_qb);
    cudaGetSymbolAddress((void**)&kvb, g_kvb);
    cudaGetSymbolAddress((void**)&bqkv, g_bqkv);
    __nv_bfloat16 *xh,*xl,*qah,*qal,*kvch,*kvcl,*atth,*attl;
    __nv_bfloat16 *wqkvh,*wqkvl,*wqbh,*wqbl,*wkvbh,*wkvbl,*woh,*wol;
    __nv_bfloat16 *kfh,*kfl,*vfh,*vfl;
    cudaGetSymbolAddress((void**)&xh, g_xh);   cudaGetSymbolAddress((void**)&xl, g_xl);
    cudaGetSymbolAddress((void**)&qah, g_qah); cudaGetSymbolAddress((void**)&qal, g_qal);
    cudaGetSymbolAddress((void**)&kvch, g_kvch); cudaGetSymbolAddress((void**)&kvcl, g_kvcl);
    cudaGetSymbolAddress((void**)&atth, g_atth); cudaGetSymbolAddress((void**)&attl, g_attl);
    cudaGetSymbolAddress((void**)&wqkvh, g_wqkvh); cudaGetSymbolAddress((void**)&wqkvl, g_wqkvl);
    cudaGetSymbolAddress((void**)&wqbh, g_wqbh); cudaGetSymbolAddress((void**)&wqbl, g_wqbl);
    cudaGetSymbolAddress((void**)&wkvbh, g_wkvbh); cudaGetSymbolAddress((void**)&wkvbl, g_wkvbl);
    cudaGetSymbolAddress((void**)&woh, g_woh); cudaGetSymbolAddress((void**)&wol, g_wol);
    cudaGetSymbolAddress((void**)&kfh, g_kfh); cudaGetSymbolAddress((void**)&kfl, g_kfl);
    cudaGetSymbolAddress((void**)&vfh, g_vfh); cudaGetSymbolAddress((void**)&vfl, g_vfl);

    cudaFuncSetAttribute(flash_mma, cudaFuncAttributeMaxDynamicSharedMemorySize, FL_SMEM + 128);
    cudaFuncSetAttribute(gemm_bf, cudaFuncAttributeMaxDynamicSharedMemorySize, GB_SMEM);

    dim3 t256(256);

    // weight/x conversions (wqa+wkva go into the combined buffer)
    cvt_hilo<<<(QLORA*DIMX)/1024, t256>>>(wqa, wqkvh, wqkvl, QLORA*DIMX);
    cvt_hilo<<<(576*DIMX)/1024, t256>>>(wkva, wqkvh + (size_t)QLORA*DIMX, wqkvl + (size_t)QLORA*DIMX, 576*DIMX);
    cvt_hilo<<<(3072*QLORA)/1024, t256>>>(wqb, wqbh, wqbl, 3072*QLORA);
    cvt_hilo<<<(4096*KVLORA)/1024, t256>>>(wkvb, wkvbh, wkvbl, 4096*KVLORA);
    cvt_hilo<<<(DIMX*2048)/1024, t256>>>(wo, woh, wol, DIMX*2048);
    cvt_hilo<<<(ROWS*DIMX)/1024, t256>>>(x, xh, xl, ROWS*DIMX);
    combine_bias<<<(QKVW+255)/256, t256>>>(wqa_b, wkva_b, bqkv);

    // 1. merged qkv = x @ [wq_a; wkv_a]^T + b   (4096 x 2112, K=2048)
    gemm_bf<<<dim3((QKVW+127)/128, ROWS/128), t256, GB_SMEM>>>(xh, xl, DIMX, wqkvh, wqkvl, DIMX, bqkv, qkv, QKVW, QKVW, DIMX);
    // 2. rmsnorm(q) -> qah/qal
    rmsnorm_hilo<<<ROWS, t256>>>(qkv, qah, qal, qnw, QLORA, QKVW, QLORA);
    // 3. q_b
    gemm_bf<<<dim3(3072/128, ROWS/128), t256, GB_SMEM>>>(qah, qal, QLORA, wqbh, wqbl, QLORA, wqb_b, qbp, 3072, 3072, QLORA);
    // 4. RoPE (qb heads + k_pe inside qkv)
    rope_kernel<<<ROWS, t256>>>(qbp, qkv);
    // 5. rmsnorm(kv_c) -> kvch/kvcl
    rmsnorm_hilo<<<ROWS, t256>>>(qkv + QLORA, kvch, kvcl, kvnw, KVLORA, QKVW, KVLORA);
    // 6. kvb
    gemm_bf<<<dim3(4096/128, ROWS/128), t256, GB_SMEM>>>(kvch, kvcl, KVLORA, wkvbh, wkvbl, KVLORA, wkvb_b, kvb, 4096, 4096, KVLORA);
    // 7. head-major K/V bf16 planes
    cvt_kv<<<ROWS, t256>>>(kvb, qkv, kfh, kfl, vfh, vfl);
    // 8. flash
    flash_mma<<<dim3(SEQL/128, NHEADS, BSZ), t256, FL_SMEM + 128>>>(qbp, kfh, kfl, vfh, vfl, atth, attl);
    // 9. out
    gemm_bf<<<dim3(2048/128, ROWS/128), t256, GB_SMEM>>>(atth, attl, 2048, woh, wol, 2048, wo_b, out, 2048, 2048, DIMX);
}

// round 10
// speedup vs baseline: 1.0378x; 1.0094x over previous
#include <cuda_runtime.h>
#include <cuda_bf16.h>
#include <cstdint>
#include <math.h>

#define SEQL   2048
#define BSZ    2
#define ROWS   (BSZ*SEQL)          // 4096
#define DIMX   2048
#define QLORA  1536
#define KVLORA 512
#define NHEADS 16
#define QKHD   192
#define NOPE_D 128
#define ROPE_D 64
#define VHD    128
#define QKVW   2112                // 1536 q + 512 kv_c + 64 k_pe

// ---------------- scratch (static device globals; no allocation) ----------------
__device__ float g_qkv[ROWS*QKVW];                 // merged q_a | kv_c | k_pe (fp32)
__device__ float g_qb [ROWS*(NHEADS*QKHD)];
__device__ float g_bqkv[QKVW];

__device__ __nv_bfloat16 g_xh  [ROWS*DIMX],   g_xl  [ROWS*DIMX];
__device__ __nv_bfloat16 g_qah [ROWS*QLORA],  g_qal [ROWS*QLORA];
__device__ __nv_bfloat16 g_kvch[ROWS*KVLORA], g_kvcl[ROWS*KVLORA];
__device__ __nv_bfloat16 g_atth[ROWS*2048],   g_attl[ROWS*2048];
__device__ __nv_bfloat16 g_wqkvh[QKVW*DIMX],  g_wqkvl[QKVW*DIMX];
__device__ __nv_bfloat16 g_wqbh[3072*QLORA],  g_wqbl[3072*QLORA];
__device__ __nv_bfloat16 g_wkvbh[4096*KVLORA],g_wkvbl[4096*KVLORA];
__device__ __nv_bfloat16 g_woh [DIMX*2048],   g_wol [DIMX*2048];
// head-major bf16 K-full (192, rope folded) and V planes for flash
__device__ __nv_bfloat16 g_kfh[ROWS*NHEADS*QKHD], g_kfl[ROWS*NHEADS*QKHD];
__device__ __nv_bfloat16 g_vfh[ROWS*NHEADS*VHD],  g_vfl[ROWS*NHEADS*VHD];

__device__ __forceinline__ uint32_t smem_to_u32(const void* p) {
    uint32_t a;
    asm("{ .reg .u64 t; cvta.to.shared.u64 t, %1; cvt.u32.u64 %0, t; }" : "=r"(a) : "l"(p));
    return a;
}
#define SWZ(x)   ((x) ^ (((x) >> 3) & 0x70))    // 128B-row swizzle (flash)
#define SWZ64(x) ((x) ^ (((x) >> 3) & 0x30))    // 64B-row swizzle (gemm K32)

__device__ __forceinline__ void ldmatrix_x4(uint32_t* r, uint32_t addr) {
    asm volatile("ldmatrix.sync.aligned.m8n8.x4.shared.b16 {%0,%1,%2,%3}, [%4];"
        : "=r"(r[0]), "=r"(r[1]), "=r"(r[2]), "=r"(r[3]) : "r"(addr));
}
__device__ __forceinline__ void ldmatrix_x4_trans(uint32_t* r, uint32_t addr) {
    asm volatile("ldmatrix.sync.aligned.m8n8.x4.trans.shared.b16 {%0,%1,%2,%3}, [%4];"
        : "=r"(r[0]), "=r"(r[1]), "=r"(r[2]), "=r"(r[3]) : "r"(addr));
}
__device__ __forceinline__ void mma_bf16(float* c, const uint32_t* a, uint32_t b0, uint32_t b1) {
    asm volatile(
        "mma.sync.aligned.m16n8k16.row.col.f32.bf16.bf16.f32 "
        "{%0,%1,%2,%3}, {%4,%5,%6,%7}, {%8,%9}, {%0,%1,%2,%3};"
        : "+f"(c[0]), "+f"(c[1]), "+f"(c[2]), "+f"(c[3])
        : "r"(a[0]), "r"(a[1]), "r"(a[2]), "r"(a[3]), "r"(b0), "r"(b1));
}
__device__ __forceinline__ uint32_t pack_bf16x2(float lo, float hi) {
    __nv_bfloat162 h = __floats2bfloat162_rn(lo, hi);
    return *reinterpret_cast<uint32_t*>(&h);
}
__device__ __forceinline__ void cp_async16(uint32_t dst, const void* src) {
    asm volatile("cp.async.cg.shared.global [%0], [%1], 16;" :: "r"(dst), "l"(src));
}
#define CP_COMMIT() asm volatile("cp.async.commit_group;" ::: "memory")
#define CP_WAIT1()  asm volatile("cp.async.wait_group 1;" ::: "memory")
#define CP_WAIT0()  asm volatile("cp.async.wait_group 0;" ::: "memory")

// ---------------- fp32 -> bf16 hi/lo planar converter ----------------
__global__ __launch_bounds__(256)
void cvt_hilo(const float* __restrict__ s, __nv_bfloat16* __restrict__ hi,
              __nv_bfloat16* __restrict__ lo, int n)
{
    int i = (blockIdx.x * 256 + threadIdx.x) * 4;
    if (i >= n) return;
    float4 v = *reinterpret_cast<const float4*>(s + i);
    __nv_bfloat162 h01 = __floats2bfloat162_rn(v.x, v.y);
    __nv_bfloat162 h23 = __floats2bfloat162_rn(v.z, v.w);
    __nv_bfloat162 l01 = __floats2bfloat162_rn(v.x - __bfloat162float(h01.x),
                                               v.y - __bfloat162float(h01.y));
    __nv_bfloat162 l23 = __floats2bfloat162_rn(v.z - __bfloat162float(h23.x),
                                               v.w - __bfloat162float(h23.y));
    *reinterpret_cast<uint2*>(hi + i) =
        make_uint2(*reinterpret_cast<uint32_t*>(&h01), *reinterpret_cast<uint32_t*>(&h23));
    *reinterpret_cast<uint2*>(lo + i) =
        make_uint2(*reinterpret_cast<uint32_t*>(&l01), *reinterpret_cast<uint32_t*>(&l23));
}

// ---------------- combine biases for merged qkv gemm ----------------
__global__ __launch_bounds__(256)
void combine_bias(const float* __restrict__ bq, const float* __restrict__ bkv,
                  float* __restrict__ dst)
{
    int i = blockIdx.x * 256 + threadIdx.x;
    if (i < QKVW) dst[i] = (i < QLORA) ? bq[i] : bkv[i - QLORA];
}

// ============ cp.async 3-stage split-bf16 HMMA GEMM, CTA 128x128, K-tile 32 ============
#define GB_STAGE 32768
#define GB_SMEM  (3*GB_STAGE + 128)

// shared mainloop body as a macro so gemm_bf / gemm_bf_kv stay identical
#define GB_MAINLOOP(ACCDECL)                                                    \
    extern __shared__ char smraw[];                                             \
    uint32_t sb0 = smem_to_u32(smraw);                                          \
    uint32_t sb = (sb0 + 127u) & ~127u;                                         \
    const int tid  = threadIdx.x;                                               \
    const int lane = tid & 31;                                                  \
    const int wid  = tid >> 5;                                                  \
    const int bm = blockIdx.y * 128;                                            \
    const int bn = blockIdx.x * 128;                                            \
    const int wm = (wid & 3) * 32;                                              \
    const int wn = (wid >> 2) * 64;                                             \
    const int nk = K >> 5;                                                      \
    ACCDECL                                                                     \
    GB_ISSUE(0); CP_COMMIT();                                                   \
    if (nk > 1) { GB_ISSUE(1); }                                                \
    CP_COMMIT();                                                                \
    for (int kt = 0; kt < nk; kt++) {                                           \
        CP_WAIT1();                                                             \
        __syncthreads();                                                        \
        const uint32_t baseA = sb + (uint32_t)(kt % 3) * GB_STAGE;              \
        const uint32_t baseB = baseA + 16384u;                                  \
        _Pragma("unroll")                                                       \
        for (int k16 = 0; k16 < 2; k16++) {                                     \
            uint32_t ah[2][4], al[2][4];                                        \
            _Pragma("unroll")                                                   \
            for (int mt = 0; mt < 2; mt++) {                                    \
                uint32_t row = wm + mt*16 + (lane & 15);                        \
                uint32_t off = SWZ64(row*64u + (uint32_t)(k16*32) + ((lane >> 4) << 4)); \
                ldmatrix_x4(ah[mt], baseA + off);                               \
                ldmatrix_x4(al[mt], baseA + 8192u + off);                       \
            }                                                                   \
            _Pragma("unroll")                                                   \
            for (int ng = 0; ng < 4; ng++) {                                    \
                uint32_t bh[4], bl[4];                                          \
                uint32_t nrow = wn + ng*16 + ((lane >> 4) << 3) + (lane & 7);   \
                uint32_t off = SWZ64(nrow*64u + (uint32_t)(k16*32) + (((lane >> 3) & 1) << 4)); \
                ldmatrix_x4(bh, baseB + off);                                   \
                ldmatrix_x4(bl, baseB + 8192u + off);                           \
                _Pragma("unroll")                                               \
                for (int mt = 0; mt < 2; mt++) {                                \
                    float* a0 = acc[mt][2*ng];                                  \
                    float* a1 = acc[mt][2*ng+1];                                \
                    mma_bf16(a0, ah[mt], bh[0], bh[1]);                         \
                    mma_bf16(a0, ah[mt], bl[0], bl[1]);                         \
                    mma_bf16(a0, al[mt], bh[0], bh[1]);                         \
                    mma_bf16(a1, ah[mt], bh[2], bh[3]);                         \
                    mma_bf16(a1, ah[mt], bl[2], bl[3]);                         \
                    mma_bf16(a1, al[mt], bh[2], bh[3]);                         \
                }                                                               \
            }                                                                   \
        }                                                                       \
        __syncthreads();                                                        \
        if (kt + 2 < nk) { GB_ISSUE(kt + 2); }                                  \
        CP_COMMIT();                                                            \
    }

#define GB_ACCDECL \
    float acc[2][8][4]; \
    _Pragma("unroll") \
    for (int mt = 0; mt < 2; mt++) \
        _Pragma("unroll") \
        for (int nt = 0; nt < 8; nt++) \
            _Pragma("unroll") \
            for (int q = 0; q < 4; q++) acc[mt][nt][q] = 0.f;

#define GB_ISSUE(kt_) do {                                                      \
        const uint32_t stb = sb + (uint32_t)((kt_) % 3) * GB_STAGE;             \
        const int k0_ = (kt_) << 5;                                             \
        _Pragma("unroll")                                                       \
        for (int i = 0; i < 8; i++) {                                           \
            const int plane = i >> 1;                                           \
            const int idx = ((i & 1) << 8) + tid;                               \
            const int r = idx >> 2;                                             \
            const int c = idx & 3;                                              \
            uint32_t dst = stb + (uint32_t)plane*8192u                          \
                         + SWZ64((uint32_t)(r*64 + c*16));                      \
            const __nv_bfloat16* srcp;                                          \
            if (plane == 0)      srcp = Ah + (size_t)(bm + r)*lda + k0_ + c*8;  \
            else if (plane == 1) srcp = Al + (size_t)(bm + r)*lda + k0_ + c*8;  \
            else {                                                              \
                int rr = bn + r; if (rr >= Nn) rr = Nn - 1;                     \
                srcp = (plane == 2 ? Bh : Bl) + (size_t)rr*ldw + k0_ + c*8;     \
            }                                                                   \
            cp_async16(dst, srcp);                                              \
        }                                                                       \
    } while (0)

__global__ __launch_bounds__(256, 2)
void gemm_bf(const __nv_bfloat16* __restrict__ Ah, const __nv_bfloat16* __restrict__ Al, int lda,
             const __nv_bfloat16* __restrict__ Bh, const __nv_bfloat16* __restrict__ Bl, int ldw,
             const float* __restrict__ bias,
             float* __restrict__ C, int ldc,
             int Nn, int K)
{
    GB_MAINLOOP(GB_ACCDECL)

    // ---- fp32 epilogue ----
#pragma unroll
    for (int nt = 0; nt < 8; nt++) {
        int col = bn + wn + nt*8 + (lane & 3)*2;
        if (col >= Nn) continue;
        float bx = bias[col], by = bias[col+1];
#pragma unroll
        for (int mt = 0; mt < 2; mt++) {
            int row = bm + wm + mt*16 + (lane >> 2);
            *reinterpret_cast<float2*>(C + (size_t)row*ldc + col) =
                make_float2(acc[mt][nt][0] + bx, acc[mt][nt][1] + by);
            *reinterpret_cast<float2*>(C + (size_t)(row+8)*ldc + col) =
                make_float2(acc[mt][nt][2] + bx, acc[mt][nt][3] + by);
        }
    }
}

// kvb GEMM: epilogue converts directly into head-major bf16 hi/lo K-nope / V planes
__global__ __launch_bounds__(256, 2)
void gemm_bf_kv(const __nv_bfloat16* __restrict__ Ah, const __nv_bfloat16* __restrict__ Al, int lda,
                const __nv_bfloat16* __restrict__ Bh, const __nv_bfloat16* __restrict__ Bl, int ldw,
                const float* __restrict__ bias,
                __nv_bfloat16* __restrict__ kfh, __nv_bfloat16* __restrict__ kfl,
                __nv_bfloat16* __restrict__ vfh, __nv_bfloat16* __restrict__ vfl,
                int Nn, int K)
{
    GB_MAINLOOP(GB_ACCDECL)

    // ---- fused epilogue: col = h*256 + d; d<128 -> K-nope plane, else V plane ----
#pragma unroll
    for (int nt = 0; nt < 8; nt++) {
        int col = bn + wn + nt*8 + (lane & 3)*2;
        float bx = bias[col], by = bias[col+1];
        int hh = col >> 8;
        int d  = col & 255;
#pragma unroll
        for (int mt = 0; mt < 2; mt++) {
            int row = bm + wm + mt*16 + (lane >> 2);
#pragma unroll
            for (int half = 0; half < 2; half++) {
                float v0 = acc[mt][nt][half*2+0] + bx;
                float v1 = acc[mt][nt][half*2+1] + by;
                int r = row + half*8;
                uint32_t hpk = pack_bf16x2(v0, v1);
                __nv_bfloat162 hv = *reinterpret_cast<__nv_bfloat162*>(&hpk);
                uint32_t lpk = pack_bf16x2(v0 - __bfloat162float(hv.x),
                                           v1 - __bfloat162float(hv.y));
                if (d < 128) {
                    size_t idx = ((size_t)r*NHEADS + hh)*QKHD + d;
                    *reinterpret_cast<uint32_t*>(kfh + idx) = hpk;
                    *reinterpret_cast<uint32_t*>(kfl + idx) = lpk;
                } else {
                    size_t idx = ((size_t)r*NHEADS + hh)*VHD + (d - 128);
                    *reinterpret_cast<uint32_t*>(vfh + idx) = hpk;
                    *reinterpret_cast<uint32_t*>(vfl + idx) = lpk;
                }
            }
        }
    }
}

// ---------------- RMSNorm -> bf16 hi/lo planar ----------------
__global__ __launch_bounds__(256)
void rmsnorm_hilo(const float* __restrict__ src,
                  __nv_bfloat16* __restrict__ hi, __nv_bfloat16* __restrict__ lo,
                  const float* __restrict__ w, int width, int sstride, int dstride)
{
    int row = blockIdx.x;
    const float* s = src + (size_t)row * sstride;

    float ss = 0.f;
    for (int c = threadIdx.x; c < width; c += blockDim.x) { float v = s[c]; ss += v*v; }

    __shared__ float red[8];
#pragma unroll
    for (int off = 16; off; off >>= 1) ss += __shfl_xor_sync(0xffffffffu, ss, off);
    int warp = threadIdx.x >> 5;
    if ((threadIdx.x & 31) == 0) red[warp] = ss;
    __syncthreads();
    if (warp == 0) {
        float v = (threadIdx.x < 8) ? red[threadIdx.x] : 0.f;
#pragma unroll
        for (int off = 4; off; off >>= 1) v += __shfl_xor_sync(0xffffffffu, v, off);
        if (threadIdx.x == 0) red[0] = v;
    }
    __syncthreads();
    float scale = rsqrtf(red[0] / (float)width + 1e-6f);
    __nv_bfloat16* dh = hi + (size_t)row * dstride;
    __nv_bfloat16* dl = lo + (size_t)row * dstride;
    for (int c = threadIdx.x; c < width; c += blockDim.x) {
        float v = s[c] * scale * w[c];
        __nv_bfloat16 hv = __float2bfloat16_rn(v);
        dh[c] = hv;
        dl[c] = __float2bfloat16_rn(v - __bfloat162float(hv));
    }
}

// ---------------- RoPE (qb heads + k_pe; k_pe also emitted to K planes) ----------------
__global__ __launch_bounds__(256)
void rope_kernel(float* __restrict__ qb, float* __restrict__ qkv,
                 __nv_bfloat16* __restrict__ kfh, __nv_bfloat16* __restrict__ kfl)
{
    int row = blockIdx.x;
    int s = row & (SEQL - 1);
    for (int p = threadIdx.x; p < 544; p += blockDim.x) {
        int d = p & 31;
        float ang = (float)s * powf(10000.f, -(float)d * (1.f/32.f));
        float sn, c;
        sincosf(ang, &sn, &c);
        if (p < 512) {
            int hh = p >> 5;
            float* base = qb + (size_t)row*(NHEADS*QKHD) + hh*QKHD + NOPE_D;
            float x1 = base[d], x2 = base[d+32];
            base[d]    = x1*c - x2*sn;
            base[d+32] = x2*c + x1*sn;
        } else {
            float* base = qkv + (size_t)row*QKVW + 2048;
            float x1 = base[d], x2 = base[d+32];
            float r1 = x1*c - x2*sn;
            float r2 = x2*c + x1*sn;
            base[d]    = r1;
            base[d+32] = r2;
            __nv_bfloat16 h1 = __float2bfloat16_rn(r1);
            __nv_bfloat16 l1 = __float2bfloat16_rn(r1 - __bfloat162float(h1));
            __nv_bfloat16 h2 = __float2bfloat16_rn(r2);
            __nv_bfloat16 l2 = __float2bfloat16_rn(r2 - __bfloat162float(h2));
#pragma unroll
            for (int hh = 0; hh < NHEADS; hh++) {
                size_t idx = ((size_t)row*NHEADS + hh)*QKHD + 128 + d;
                kfh[idx]      = h1;
                kfl[idx]      = l1;
                kfh[idx + 32] = h2;
                kfl[idx + 32] = l2;
            }
        }
    }
}

// ============ Flash attention via mma.sync (split-bf16), cp.async K/V ============
#define FL_QH 0
#define FL_QL 49152
#define FL_KH 98304
#define FL_KL 122880
#define FL_VH 147456
#define FL_VL 163840
#define FL_SMEM 180224

__global__ __launch_bounds__(256, 1)
void flash_mma(const float* __restrict__ qb,
               const __nv_bfloat16* __restrict__ kfh, const __nv_bfloat16* __restrict__ kfl,
               const __nv_bfloat16* __restrict__ vfh, const __nv_bfloat16* __restrict__ vfl,
               __nv_bfloat16* __restrict__ atth,
               __nv_bfloat16* __restrict__ attl)
{
    extern __shared__ char smraw[];
    uint32_t sb0 = smem_to_u32(smraw);
    uint32_t sb = (sb0 + 127u) & ~127u;
    char* smp = smraw + (sb - sb0);

    const int qt = blockIdx.x;
    const int h  = blockIdx.y;
    const int b  = blockIdx.z;
    const int s0 = qt * 128;
    const int bb = b * SEQL;
    const int tid  = threadIdx.x;
    const int lane = tid & 31;
    const int wid  = tid >> 5;
    const int wrow = wid * 16;
    const float scale = 0.07216878364870323f;

#pragma unroll
    for (int i = 0; i < 24; i++) {
        int idx = tid + i*256;
        int row = idx / 48;
        int d = (idx - row*48) * 4;
        float4 v = *reinterpret_cast<const float4*>(
            qb + (size_t)(bb + s0 + row)*3072 + h*192 + d);
        v.x *= scale; v.y *= scale; v.z *= scale; v.w *= scale;
        int ch = d >> 6, dc = d & 63;
        uint32_t off = SWZ((uint32_t)(row*128 + dc*2));
        __nv_bfloat162 h01 = __floats2bfloat162_rn(v.x, v.y);
        __nv_bfloat162 h23 = __floats2bfloat162_rn(v.z, v.w);
        __nv_bfloat162 l01 = __floats2bfloat162_rn(v.x - __bfloat162float(h01.x),
                                                   v.y - __bfloat162float(h01.y));
        __nv_bfloat162 l23 = __floats2bfloat162_rn(v.z - __bfloat162float(h23.x),
                                                   v.w - __bfloat162float(h23.y));
        *reinterpret_cast<uint2*>(smp + FL_QH + ch*16384 + off) =
            make_uint2(*reinterpret_cast<uint32_t*>(&h01), *reinterpret_cast<uint32_t*>(&h23));
        *reinterpret_cast<uint2*>(smp + FL_QL + ch*16384 + off) =
            make_uint2(*reinterpret_cast<uint32_t*>(&l01), *reinterpret_cast<uint32_t*>(&l23));
    }

    float oc[16][4];
#pragma unroll
    for (int nt = 0; nt < 16; nt++)
#pragma unroll
        for (int q = 0; q < 4; q++) oc[nt][q] = 0.f;
    float m0 = -1e30f, m1 = -1e30f, l0 = 0.f, l1 = 0.f;

    const int rg0 = s0 + wrow + (lane >> 2);
    const int rg1 = rg0 + 8;
    const int nkt = 2*qt + 2;

    for (int kt = 0; kt < nkt; kt++) {
        if (kt > 0) __syncthreads();
        const int ks0 = kt * 64;

#pragma unroll
        for (int i = 0; i < 12; i++) {
            int idx = tid + i*256;
            int cidx = idx;
            const __nv_bfloat16* src;
            uint32_t base;
            if (cidx < 1536) { src = kfh; base = (uint32_t)FL_KH; }
            else             { src = kfl; base = (uint32_t)FL_KL; cidx -= 1536; }
            int row = cidx / 24;
            int c = cidx - row*24;
            int ch = c >> 3;
            int dc8 = (c & 7) * 8;
            uint32_t dst = sb + base + ch*8192u + SWZ((uint32_t)(row*128 + dc8*2));
            cp_async16(dst, src + ((size_t)(bb + ks0 + row)*NHEADS + h)*QKHD + ch*64 + dc8);
        }
#pragma unroll
        for (int i = 0; i < 8; i++) {
            int idx = tid + i*256;
            int cidx = idx;
            const __nv_bfloat16* src;
            uint32_t base;
            if (cidx < 1024) { src = vfh; base = (uint32_t)FL_VH; }
            else             { src = vfl; base = (uint32_t)FL_VL; cidx -= 1024; }
            int row = cidx >> 4;
            int c = cidx & 15;
            int ch = c >> 3;
            int dc8 = (c & 7) * 8;
            uint32_t dst = sb + base + ch*8192u + SWZ((uint32_t)(row*128 + dc8*2));
            cp_async16(dst, src + ((size_t)(bb + ks0 + row)*NHEADS + h)*VHD + ch*64 + dc8);
        }
        CP_COMMIT();
        CP_WAIT0();
        __syncthreads();

        if (ks0 > s0 + wrow + 15) continue;

        float sc[8][4];
#pragma unroll
        for (int nt = 0; nt < 8; nt++)
#pragma unroll
            for (int q = 0; q < 4; q++) sc[nt][q] = 0.f;

#pragma unroll
        for (int ks = 0; ks < 12; ks++) {
            int ch = ks >> 2;
            uint32_t kb = (uint32_t)((ks & 3) * 32);
            uint32_t ah[4], al[4];
            {
                uint32_t row = wrow + (lane & 15);
                uint32_t off = SWZ(row*128u + kb + ((lane >> 4) << 4));
                ldmatrix_x4(ah, sb + FL_QH + ch*16384 + off);
                ldmatrix_x4(al, sb + FL_QL + ch*16384 + off);
            }
            uint32_t bh[16], bl[16];
#pragma unroll
            for (int ng = 0; ng < 4; ng++) {
                uint32_t nrow = ng*16 + ((lane >> 4) << 3) + (lane & 7);
                uint32_t off = SWZ(nrow*128u + kb + (((lane >> 3) & 1) << 4));
                ldmatrix_x4(&bh[ng*4], sb + FL_KH + ch*8192 + off);
                ldmatrix_x4(&bl[ng*4], sb + FL_KL + ch*8192 + off);
            }
#pragma unroll
            for (int nt = 0; nt < 8; nt++) {
                mma_bf16(sc[nt], ah, bh[nt*2], bh[nt*2+1]);
                mma_bf16(sc[nt], ah, bl[nt*2], bl[nt*2+1]);
                mma_bf16(sc[nt], al, bh[nt*2], bh[nt*2+1]);
            }
        }

        if (ks0 + 63 > s0 + wrow) {
#pragma unroll
            for (int nt = 0; nt < 8; nt++) {
                int colg = ks0 + nt*8 + (lane & 3)*2;
                if (colg     > rg0) sc[nt][0] = -1e30f;
                if (colg + 1 > rg0) sc[nt][1] = -1e30f;
                if (colg     > rg1) sc[nt][2] = -1e30f;
                if (colg + 1 > rg1) sc[nt][3] = -1e30f;
            }
        }

        float mx0 = -1e30f, mx1 = -1e30f;
#pragma unroll
        for (int nt = 0; nt < 8; nt++) {
            mx0 = fmaxf(mx0, fmaxf(sc[nt][0], sc[nt][1]));
            mx1 = fmaxf(mx1, fmaxf(sc[nt][2], sc[nt][3]));
        }
        mx0 = fmaxf(mx0, __shfl_xor_sync(0xffffffffu, mx0, 1));
        mx0 = fmaxf(mx0, __shfl_xor_sync(0xffffffffu, mx0, 2));
        mx1 = fmaxf(mx1, __shfl_xor_sync(0xffffffffu, mx1, 1));
        mx1 = fmaxf(mx1, __shfl_xor_sync(0xffffffffu, mx1, 2));
        float mn0 = fmaxf(m0, mx0), mn1 = fmaxf(m1, mx1);
        float a0 = __expf(m0 - mn0), a1 = __expf(m1 - mn1);
        m0 = mn0; m1 = mn1;
        float rs0 = 0.f, rs1 = 0.f;
#pragma unroll
        for (int nt = 0; nt < 8; nt++) {
            sc[nt][0] = __expf(sc[nt][0] - mn0); rs0 += sc[nt][0];
            sc[nt][1] = __expf(sc[nt][1] - mn0); rs0 += sc[nt][1];
            sc[nt][2] = __expf(sc[nt][2] - mn1); rs1 += sc[nt][2];
            sc[nt][3] = __expf(sc[nt][3] - mn1); rs1 += sc[nt][3];
        }
        rs0 += __shfl_xor_sync(0xffffffffu, rs0, 1);
        rs0 += __shfl_xor_sync(0xffffffffu, rs0, 2);
        rs1 += __shfl_xor_sync(0xffffffffu, rs1, 1);
        rs1 += __shfl_xor_sync(0xffffffffu, rs1, 2);
        l0 = l0*a0 + rs0;
        l1 = l1*a1 + rs1;
#pragma unroll
        for (int nt = 0; nt < 16; nt++) {
            oc[nt][0] *= a0; oc[nt][1] *= a0;
            oc[nt][2] *= a1; oc[nt][3] *= a1;
        }

#pragma unroll
        for (int kp = 0; kp < 4; kp++) {
            uint32_t ph[4], pl[4];
            {
                float p0 = sc[2*kp][0],  p1 = sc[2*kp][1];
                float p2 = sc[2*kp][2],  p3 = sc[2*kp][3];
                float p4 = sc[2*kp+1][0], p5 = sc[2*kp+1][1];
                float p6 = sc[2*kp+1][2], p7 = sc[2*kp+1][3];
                ph[0] = pack_bf16x2(p0, p1);
                ph[1] = pack_bf16x2(p2, p3);
                ph[2] = pack_bf16x2(p4, p5);
                ph[3] = pack_bf16x2(p6, p7);
                __nv_bfloat162* hp;
                hp = reinterpret_cast<__nv_bfloat162*>(&ph[0]);
                pl[0] = pack_bf16x2(p0 - __bfloat162float(hp->x), p1 - __bfloat162float(hp->y));
                hp = reinterpret_cast<__nv_bfloat162*>(&ph[1]);
                pl[1] = pack_bf16x2(p2 - __bfloat162float(hp->x), p3 - __bfloat162float(hp->y));
                hp = reinterpret_cast<__nv_bfloat162*>(&ph[2]);
                pl[2] = pack_bf16x2(p4 - __bfloat162float(hp->x), p5 - __bfloat162float(hp->y));
                hp = reinterpret_cast<__nv_bfloat162*>(&ph[3]);
                pl[3] = pack_bf16x2(p6 - __bfloat162float(hp->x), p7 - __bfloat162float(hp->y));
            }
#pragma unroll
            for (int ng = 0; ng < 8; ng++) {
                int ch = ng >> 2;
                uint32_t n0 = (uint32_t)((ng & 3)*16) + ((lane >> 4) << 3);
                uint32_t krow = (uint32_t)(kp*16) + (lane & 15);
                uint32_t off = SWZ(krow*128u + n0*2u);
                uint32_t vh[4], vl[4];
                ldmatrix_x4_trans(vh, sb + FL_VH + ch*8192 + off);
                ldmatrix_x4_trans(vl, sb + FL_VL + ch*8192 + off);
                mma_bf16(oc[ng*2],   ph, vh[0], vh[1]);
                mma_bf16(oc[ng*2],   ph, vl[0], vl[1]);
                mma_bf16(oc[ng*2],   pl, vh[0], vh[1]);
                mma_bf16(oc[ng*2+1], ph, vh[2], vh[3]);
                mma_bf16(oc[ng*2+1], ph, vl[2], vl[3]);
                mma_bf16(oc[ng*2+1], pl, vh[2], vh[3]);
            }
        }
    }

    float inv0 = 1.f / l0, inv1 = 1.f / l1;
    int row0 = bb + s0 + wrow + (lane >> 2);
    int row1 = row0 + 8;
#pragma unroll
    for (int nt = 0; nt < 16; nt++) {
        int col = h*128 + nt*8 + (lane & 3)*2;
        float o0 = oc[nt][0]*inv0, o1 = oc[nt][1]*inv0;
        float o2 = oc[nt][2]*inv1, o3 = oc[nt][3]*inv1;
        uint32_t h0 = pack_bf16x2(o0, o1);
        __nv_bfloat162 hv0 = *reinterpret_cast<__nv_bfloat162*>(&h0);
        uint32_t l0p = pack_bf16x2(o0 - __bfloat162float(hv0.x), o1 - __bfloat162float(hv0.y));
        uint32_t h1 = pack_bf16x2(o2, o3);
        __nv_bfloat162 hv1 = *reinterpret_cast<__nv_bfloat162*>(&h1);
        uint32_t l1p = pack_bf16x2(o2 - __bfloat162float(hv1.x), o3 - __bfloat162float(hv1.y));
        *reinterpret_cast<uint32_t*>(atth + (size_t)row0*2048 + col) = h0;
        *reinterpret_cast<uint32_t*>(attl + (size_t)row0*2048 + col) = l0p;
        *reinterpret_cast<uint32_t*>(atth + (size_t)row1*2048 + col) = h1;
        *reinterpret_cast<uint32_t*>(attl + (size_t)row1*2048 + col) = l1p;
    }
}

// ---------------- host launcher ----------------
extern "C" void kernel_launch(void* const* d_in, const int* in_sizes, int n_in,
                              void* d_out, int out_size)
{
    const float* x      = (const float*)d_in[0];
    const float* wqa    = (const float*)d_in[1];
    const float* wqa_b  = (const float*)d_in[2];
    const float* qnw    = (const float*)d_in[3];
    const float* wqb    = (const float*)d_in[4];
    const float* wqb_b  = (const float*)d_in[5];
    const float* wkva   = (const float*)d_in[6];
    const float* wkva_b = (const float*)d_in[7];
    const float* kvnw   = (const float*)d_in[8];
    const float* wkvb   = (const float*)d_in[9];
    const float* wkvb_b = (const float*)d_in[10];
    const float* wo     = (const float*)d_in[11];
    const float* wo_b   = (const float*)d_in[12];
    float* out = (float*)d_out;

    float *qkv, *qbp, *bqkv;
    cudaGetSymbolAddress((void**)&qkv, g_qkv);
    cudaGetSymbolAddress((void**)&qbp, g_qb);
    cudaGetSymbolAddress((void**)&bqkv, g_bqkv);
    __nv_bfloat16 *xh,*xl,*qah,*qal,*kvch,*kvcl,*atth,*attl;
    __nv_bfloat16 *wqkvh,*wqkvl,*wqbh,*wqbl,*wkvbh,*wkvbl,*woh,*wol;
    __nv_bfloat16 *kfh,*kfl,*vfh,*vfl;
    cudaGetSymbolAddress((void**)&xh, g_xh);   cudaGetSymbolAddress((void**)&xl, g_xl);
    cudaGetSymbolAddress((void**)&qah, g_qah); cudaGetSymbolAddress((void**)&qal, g_qal);
    cudaGetSymbolAddress((void**)&kvch, g_kvch); cudaGetSymbolAddress((void**)&kvcl, g_kvcl);
    cudaGetSymbolAddress((void**)&atth, g_atth); cudaGetSymbolAddress((void**)&attl, g_attl);
    cudaGetSymbolAddress((void**)&wqkvh, g_wqkvh); cudaGetSymbolAddress((void**)&wqkvl, g_wqkvl);
    cudaGetSymbolAddress((void**)&wqbh, g_wqbh); cudaGetSymbolAddress((void**)&wqbl, g_wqbl);
    cudaGetSymbolAddress((void**)&wkvbh, g_wkvbh); cudaGetSymbolAddress((void**)&wkvbl, g_wkvbl);
    cudaGetSymbolAddress((void**)&woh, g_woh); cudaGetSymbolAddress((void**)&wol, g_wol);
    cudaGetSymbolAddress((void**)&kfh, g_kfh); cudaGetSymbolAddress((void**)&kfl, g_kfl);
    cudaGetSymbolAddress((void**)&vfh, g_vfh); cudaGetSymbolAddress((void**)&vfl, g_vfl);

    cudaFuncSetAttribute(flash_mma, cudaFuncAttributeMaxDynamicSharedMemorySize, FL_SMEM + 128);
    cudaFuncSetAttribute(gemm_bf, cudaFuncAttributeMaxDynamicSharedMemorySize, GB_SMEM);
    cudaFuncSetAttribute(gemm_bf_kv, cudaFuncAttributeMaxDynamicSharedMemorySize, GB_SMEM);

    dim3 t256(256);

    cvt_hilo<<<(QLORA*DIMX)/1024, t256>>>(wqa, wqkvh, wqkvl, QLORA*DIMX);
    cvt_hilo<<<(576*DIMX)/1024, t256>>>(wkva, wqkvh + (size_t)QLORA*DIMX, wqkvl + (size_t)QLORA*DIMX, 576*DIMX);
    cvt_hilo<<<(3072*QLORA)/1024, t256>>>(wqb, wqbh, wqbl, 3072*QLORA);
    cvt_hilo<<<(4096*KVLORA)/1024, t256>>>(wkvb, wkvbh, wkvbl, 4096*KVLORA);
    cvt_hilo<<<(DIMX*2048)/1024, t256>>>(wo, woh, wol, DIMX*2048);
    cvt_hilo<<<(ROWS*DIMX)/1024, t256>>>(x, xh, xl, ROWS*DIMX);
    combine_bias<<<(QKVW+255)/256, t256>>>(wqa_b, wkva_b, bqkv);

    // 1. merged qkv = x @ [wq_a; wkv_a]^T + b   (4096 x 2112, K=2048)
    gemm_bf<<<dim3((QKVW+127)/128, ROWS/128), t256, GB_SMEM>>>(xh, xl, DIMX, wqkvh, wqkvl, DIMX, bqkv, qkv, QKVW, QKVW, DIMX);
    // 2. rmsnorm(q) -> qah/qal
    rmsnorm_hilo<<<ROWS, t256>>>(qkv, qah, qal, qnw, QLORA, QKVW, QLORA);
    // 3. q_b
    gemm_bf<<<dim3(3072/128, ROWS/128), t256, GB_SMEM>>>(qah, qal, QLORA, wqbh, wqbl, QLORA, wqb_b, qbp, 3072, 3072, QLORA);
    // 4. RoPE (qb heads + k_pe; also emits K-rope bf16 planes)
    rope_kernel<<<ROWS, t256>>>(qbp, qkv, kfh, kfl);
    // 5. rmsnorm(kv_c) -> kvch/kvcl
    rmsnorm_hilo<<<ROWS, t256>>>(qkv + QLORA, kvch, kvcl, kvnw, KVLORA, QKVW, KVLORA);
    // 6. kvb GEMM with fused head-major bf16 plane epilogue
    gemm_bf_kv<<<dim3(4096/128, ROWS/128), t256, GB_SMEM>>>(kvch, kvcl, KVLORA, wkvbh, wkvbl, KVLORA, wkvb_b, kfh, kfl, vfh, vfl, 4096, KVLORA);
    // 7. flash
    flash_mma<<<dim3(SEQL/128, NHEADS, BSZ), t256, FL_SMEM + 128>>>(qbp, kfh, kfl, vfh, vfl, atth, attl);
    // 8. out
    gemm_bf<<<dim3(2048/128, ROWS/128), t256, GB_SMEM>>>(atth, attl, 2048, woh, wol, 2048, wo_b, out, 2048, 2048, DIMX);
}